// round 13
// baseline (speedup 1.0000x reference)
#include <cuda_runtime.h>
#include <cuda_fp16.h>
#include <cstdint>

#define NB 8
#define NC 512
#define NL 2048
#define NT 64
#define NJT (NL / 128)   // 16 j-tiles
#define NIT (NL / 128)   // 16 i-tiles

// Scratch (static device globals — no allocation in kernel_launch)
__device__ __half g_Qh[NB * NL * NT];
__device__ __half g_Ql[NB * NL * NT];
__device__ __half g_Kh[NB * NL * NT];
__device__ __half g_Kl[NB * NL * NT];
__device__ __half g_P[(size_t)NB * NL * NL];     // P' fp16 (scaled in-place)  64 MB
__device__ __half g_Xh[(size_t)NB * NC * NL];    // x fp16                     16 MB
__device__ float  g_sum[NB * NL];                // exact row sums of e^s
__device__ float  g_rm[NB * NJT * NIT * 128];    // per-(row, i-tile) max
__device__ float  g_w[NB * NJT * NIT * 128];     // e^{m_rt - C_j}
__device__ float  g_osc[NB * NL];                // e^{C_j} / sum_j

__device__ __forceinline__ uint32_t smem_u32(const void* p) {
    uint32_t r;
    asm("{ .reg .u64 t; cvta.to.shared.u64 t, %1; cvt.u32.u64 %0, t; }" : "=r"(r) : "l"(p));
    return r;
}
__device__ __forceinline__ void cp16(uint32_t dst, const void* src) {
    asm volatile("cp.async.cg.shared.global [%0], [%1], 16;\n" :: "r"(dst), "l"(src));
}
__device__ __forceinline__ void ldm4(uint32_t* r, uint32_t addr) {
    asm volatile("ldmatrix.sync.aligned.m8n8.x4.shared.b16 {%0,%1,%2,%3}, [%4];"
                 : "=r"(r[0]), "=r"(r[1]), "=r"(r[2]), "=r"(r[3]) : "r"(addr));
}

#define MMA_F16(ac, A, b0v, b1v)                                              \
    asm volatile("mma.sync.aligned.m16n8k16.row.col.f32.f16.f16.f32 "         \
                 "{%0,%1,%2,%3}, {%4,%5,%6,%7}, {%8,%9}, {%0,%1,%2,%3};"      \
                 : "+f"(ac[0]), "+f"(ac[1]), "+f"(ac[2]), "+f"(ac[3])         \
                 : "r"(A[0]), "r"(A[1]), "r"(A[2]), "r"(A[3]),                \
                   "r"(b0v), "r"(b1v));

// ---------------------------------------------------------------------------
// Tiny kernels
// ---------------------------------------------------------------------------
__global__ void k_zero() { g_sum[blockIdx.x * 1024 + threadIdx.x] = 0.f; }

// x -> fp16
__global__ __launch_bounds__(256) void k_half(const float* __restrict__ x) {
    const size_t e = ((size_t)blockIdx.x * 256 + threadIdx.x) * 8;
    float4 v0 = *(const float4*)(x + e);
    float4 v1 = *(const float4*)(x + e + 4);
    __half2 h[4];
    h[0] = __floats2half2_rn(v0.x, v0.y);
    h[1] = __floats2half2_rn(v0.z, v0.w);
    h[2] = __floats2half2_rn(v1.x, v1.y);
    h[3] = __floats2half2_rn(v1.z, v1.w);
    *(uint4*)(g_Xh + e) = *(const uint4*)h;
}

// per (b, jt, row): C_j = max_it m_rt; w = e^{m_rt - C_j}; osc_j = e^{C_j}/sum_j
__global__ __launch_bounds__(128) void k_prep() {
    const int b = blockIdx.x >> 4, jt = blockIdx.x & 15;
    const int r = threadIdx.x;
    const size_t base = (size_t)(b * NJT + jt) * NIT * 128 + r;
    float mv[NIT];
    float C = -1e30f;
#pragma unroll
    for (int it = 0; it < NIT; it++) {
        mv[it] = g_rm[base + it * 128];
        C = fmaxf(C, mv[it]);
    }
#pragma unroll
    for (int it = 0; it < NIT; it++)
        g_w[base + it * 128] = __expf(mv[it] - C);
    const int j = b * NL + jt * 128 + r;
    g_osc[j] = __expf(C) / g_sum[j];
}

// P[b][j][i] *= w[b][jt(j)][it(i)][j%128]  (in place, one block per row)
__global__ __launch_bounds__(256) void k_scale() {
    const int row = blockIdx.x;                 // b*NL + j
    const int b = row >> 11, j = row & (NL - 1);
    const int jt = j >> 7;
    __half* P = g_P + (size_t)row * NL;
    const int t = threadIdx.x;
    const int it = t >> 4;                      // (t*8)/128
    const float w = g_w[((size_t)(b * NJT + jt) * NIT + it) * 128 + (j & 127)];
    const __half2 wh = __float2half2_rn(w);
    uint4 v = *(uint4*)(P + t * 8);
    __half2* h = (__half2*)&v;
    h[0] = __hmul2(h[0], wh);
    h[1] = __hmul2(h[1], wh);
    h[2] = __hmul2(h[2], wh);
    h[3] = __hmul2(h[3], wh);
    *(uint4*)(P + t * 8) = v;
}

// ---------------------------------------------------------------------------
// Kernel 1 (fp16 hi/lo 3-term MMA): Q/K projection.
// ---------------------------------------------------------------------------
#define PXROW 72
#define P_XH 0
#define P_XL (64 * PXROW)
#define P_WH (2 * 64 * PXROW)
#define P_WL (2 * 64 * PXROW + 128 * PXROW)
#define SMEM_PROJ ((2 * 64 * PXROW + 2 * 128 * PXROW) * 2)   // 55296 B

__global__ __launch_bounds__(256, 2) void k_proj_mma(const float* __restrict__ x,
                                                     const float* __restrict__ W1,
                                                     const float* __restrict__ W2) {
    extern __shared__ __half smh[];
    const uint32_t sb = smem_u32(smh);
    const int tid = threadIdx.x;
    const int b = blockIdx.y;
    const int l0 = blockIdx.x * 64;
    const float* xb = x + (size_t)b * NC * NL;

    const int wid = tid >> 5, lane = tid & 31;
    const int wm = wid & 1;
    const int wn = wid >> 1;
    const int grp = lane >> 2, qid = lane & 3;
    const int rowA = (lane & 7) + ((lane >> 3) & 1) * 8;
    const int colA = (lane >> 4) * 8;
    const int rowB = (lane & 7) + (lane >> 4) * 8;
    const int colB = ((lane >> 3) & 1) * 8;

    float acc[2][4][4];
#pragma unroll
    for (int mt = 0; mt < 2; mt++)
#pragma unroll
        for (int nt = 0; nt < 4; nt++)
#pragma unroll
            for (int q = 0; q < 4; q++) acc[mt][nt][q] = 0.f;

    for (int ch = 0; ch < NC / 64; ch++) {
        const int c0 = ch * 64;
#pragma unroll
        for (int u = 0; u < 4; u++) {
            int f = tid + u * 256;
            int c = f & 63, lq = f >> 6;
            float4 v = *(const float4*)(xb + (size_t)(c0 + c) * NL + l0 + lq * 4);
            float vv[4] = {v.x, v.y, v.z, v.w};
#pragma unroll
            for (int j = 0; j < 4; j++) {
                __half h = __float2half_rn(vv[j]);
                __half l = __float2half_rn(vv[j] - __half2float(h));
                smh[P_XH + (lq * 4 + j) * PXROW + c] = h;
                smh[P_XL + (lq * 4 + j) * PXROW + c] = l;
            }
        }
#pragma unroll
        for (int u = 0; u < 8; u++) {
            int f = tid + u * 256;
            int t = f & 127, cq = f >> 7;
            const float* wsrc = (t < 64) ? (W1 + t * NC) : (W2 + (t - 64) * NC);
            float4 v = *(const float4*)(wsrc + c0 + cq * 4);
            float vv[4] = {v.x, v.y, v.z, v.w};
            __half hh[4], hl[4];
#pragma unroll
            for (int j = 0; j < 4; j++) {
                hh[j] = __float2half_rn(vv[j]);
                hl[j] = __float2half_rn(vv[j] - __half2float(hh[j]));
            }
            *(uint2*)&smh[P_WH + t * PXROW + cq * 4] = *(uint2*)hh;
            *(uint2*)&smh[P_WL + t * PXROW + cq * 4] = *(uint2*)hl;
        }
        __syncthreads();

#pragma unroll
        for (int k16 = 0; k16 < 4; k16++) {
            const int k = k16 * 16;
            uint32_t ah[2][4], al[2][4];
#pragma unroll
            for (int mt = 0; mt < 2; mt++) {
                const uint32_t ao = ((wm * 32 + mt * 16 + rowA) * PXROW + k + colA) * 2;
                ldm4(ah[mt], sb + P_XH * 2 + ao);
                ldm4(al[mt], sb + P_XL * 2 + ao);
            }
#pragma unroll
            for (int p = 0; p < 2; p++) {
                const uint32_t bo = ((wn * 32 + p * 16 + rowB) * PXROW + k + colB) * 2;
                uint32_t bh[4], bl[4];
                ldm4(bh, sb + P_WH * 2 + bo);
                ldm4(bl, sb + P_WL * 2 + bo);
#pragma unroll
                for (int e = 0; e < 2; e++) {
                    const int nt = p * 2 + e;
#pragma unroll
                    for (int mt = 0; mt < 2; mt++) {
                        MMA_F16(acc[mt][nt], ah[mt], bh[2 * e], bh[2 * e + 1]);
                        MMA_F16(acc[mt][nt], ah[mt], bl[2 * e], bl[2 * e + 1]);
                        MMA_F16(acc[mt][nt], al[mt], bh[2 * e], bh[2 * e + 1]);
                    }
                }
            }
        }
        __syncthreads();
    }

#pragma unroll
    for (int mt = 0; mt < 2; mt++) {
#pragma unroll
        for (int nt = 0; nt < 4; nt++) {
            const int t = wn * 32 + nt * 8 + qid * 2;
#pragma unroll
            for (int hrow = 0; hrow < 2; hrow++) {
                const int l = l0 + wm * 32 + mt * 16 + grp + hrow * 8;
                float v0 = acc[mt][nt][hrow * 2 + 0];
                float v1 = acc[mt][nt][hrow * 2 + 1];
                __half h0 = __float2half_rn(v0), h1 = __float2half_rn(v1);
                __half l0h = __float2half_rn(v0 - __half2float(h0));
                __half l1h = __float2half_rn(v1 - __half2float(h1));
                __half hp[2] = {h0, h1}, lp[2] = {l0h, l1h};
                const size_t off = ((size_t)b * NL + l) * NT + (t & 63);
                if (t < 64) {
                    *(uint32_t*)&g_Qh[off] = *(uint32_t*)hp;
                    *(uint32_t*)&g_Ql[off] = *(uint32_t*)lp;
                } else {
                    *(uint32_t*)&g_Kh[off] = *(uint32_t*)hp;
                    *(uint32_t*)&g_Kl[off] = *(uint32_t*)lp;
                }
            }
        }
    }
}

// ---------------------------------------------------------------------------
// Kernel 2 (fp16 hi/lo 3-term mma): P' = exp(s - m_row,tile) fp16,
// m_rt -> g_rm, exact row sums -> atomicAdd. Two-group staged tile load.
// ---------------------------------------------------------------------------
#define SROWH 72
#define STILE_H (128 * SROWH)
#define SMEM_SC (4 * STILE_H * 2)   // 73728 B

__global__ __launch_bounds__(256) void k_scores_mma() {
    extern __shared__ char smraw[];
    const uint32_t sb = smem_u32(smraw);
    const int tid = threadIdx.x;
    const int b = blockIdx.z;
    const int j0 = blockIdx.y * 128;
    const int i0 = blockIdx.x * 128;

    const __half* srcs[4] = {g_Qh + ((size_t)b * NL + j0) * NT,
                             g_Ql + ((size_t)b * NL + j0) * NT,
                             g_Kh + ((size_t)b * NL + i0) * NT,
                             g_Kl + ((size_t)b * NL + i0) * NT};
#pragma unroll
    for (int t = 0; t < 4; t++) {
#pragma unroll
        for (int u = 0; u < 2; u++) {
            int e = tid + u * 256;
            int r = e >> 2, seg = e & 3;
            cp16(sb + (t * STILE_H + r * SROWH + seg * 8) * 2,
                 srcs[t] + (size_t)r * NT + seg * 8);
        }
    }
    asm volatile("cp.async.commit_group;\n" ::: "memory");
#pragma unroll
    for (int t = 0; t < 4; t++) {
#pragma unroll
        for (int u = 0; u < 2; u++) {
            int e = tid + u * 256;
            int r = e >> 2, seg = 4 + (e & 3);
            cp16(sb + (t * STILE_H + r * SROWH + seg * 8) * 2,
                 srcs[t] + (size_t)r * NT + seg * 8);
        }
    }
    asm volatile("cp.async.commit_group;\n" ::: "memory");

    const int wid = tid >> 5, lane = tid & 31;
    const int wm = wid & 3;
    const int wn = wid >> 2;
    const int grp = lane >> 2, qid = lane & 3;
    const int rowA = (lane & 7) + ((lane >> 3) & 1) * 8;
    const int colA = (lane >> 4) * 8;
    const int rowB = (lane & 7) + (lane >> 4) * 8;
    const int colB = ((lane >> 3) & 1) * 8;

    const uint32_t qh_b = sb;
    const uint32_t ql_b = sb + STILE_H * 2;
    const uint32_t kh_b = sb + 2 * STILE_H * 2;
    const uint32_t kl_b = sb + 3 * STILE_H * 2;

    float acc[2][8][4];
#pragma unroll
    for (int mt = 0; mt < 2; mt++)
#pragma unroll
        for (int nt = 0; nt < 8; nt++)
#pragma unroll
            for (int q = 0; q < 4; q++) acc[mt][nt][q] = 0.f;

    auto compute_k16 = [&](int kh16) {
        const int k = kh16 * 16;
        uint32_t ah[2][4], al[2][4];
#pragma unroll
        for (int mt = 0; mt < 2; mt++) {
            const uint32_t ao = ((wm * 32 + mt * 16 + rowA) * SROWH + k + colA) * 2;
            ldm4(ah[mt], qh_b + ao);
            ldm4(al[mt], ql_b + ao);
        }
#pragma unroll
        for (int p = 0; p < 4; p++) {
            const uint32_t bo = ((wn * 64 + p * 16 + rowB) * SROWH + k + colB) * 2;
            uint32_t bh[4], bl[4];
            ldm4(bh, kh_b + bo);
            ldm4(bl, kl_b + bo);
#pragma unroll
            for (int e = 0; e < 2; e++) {
                const int nt = p * 2 + e;
#pragma unroll
                for (int mt = 0; mt < 2; mt++) {
                    MMA_F16(acc[mt][nt], ah[mt], bh[2 * e], bh[2 * e + 1]);
                    MMA_F16(acc[mt][nt], ah[mt], bl[2 * e], bl[2 * e + 1]);
                    MMA_F16(acc[mt][nt], al[mt], bh[2 * e], bh[2 * e + 1]);
                }
            }
        }
    };

    asm volatile("cp.async.wait_group 1;\n" ::: "memory");
    __syncthreads();
    compute_k16(0);
    compute_k16(1);
    asm volatile("cp.async.wait_group 0;\n" ::: "memory");
    __syncthreads();
    compute_k16(2);
    compute_k16(3);

    // per-row (within tile) max: quad reduce, then combine the 2 wn warps
    float lmax[2][2];
#pragma unroll
    for (int mt = 0; mt < 2; mt++)
#pragma unroll
        for (int h = 0; h < 2; h++) {
            float m = -1e30f;
#pragma unroll
            for (int nt = 0; nt < 8; nt++)
                m = fmaxf(m, fmaxf(acc[mt][nt][2 * h], acc[mt][nt][2 * h + 1]));
            m = fmaxf(m, __shfl_xor_sync(0xffffffffu, m, 1));
            m = fmaxf(m, __shfl_xor_sync(0xffffffffu, m, 2));
            lmax[mt][h] = m;
        }
    float* red = (float*)smraw;
    __syncthreads();
    if (qid == 0) {
#pragma unroll
        for (int mt = 0; mt < 2; mt++)
#pragma unroll
            for (int h = 0; h < 2; h++)
                red[(((wn * 4 + wm) * 2 + mt) * 2 + h) * 8 + grp] = lmax[mt][h];
    }
    __syncthreads();

    __half* Pb = g_P + (size_t)b * NL * NL;
#pragma unroll
    for (int mt = 0; mt < 2; mt++)
#pragma unroll
        for (int h = 0; h < 2; h++) {
            const float mx = fmaxf(lmax[mt][h],
                red[((((1 - wn) * 4 + wm) * 2 + mt) * 2 + h) * 8 + grp]);
            const int r = j0 + wm * 32 + mt * 16 + grp + h * 8;
            float rs = 0.f;
#pragma unroll
            for (int nt = 0; nt < 8; nt++) {
                const int col = i0 + wn * 64 + nt * 8 + qid * 2;
                float e0 = __expf(acc[mt][nt][2 * h] - mx);
                float e1 = __expf(acc[mt][nt][2 * h + 1] - mx);
                rs += e0 + e1;
                *(__half2*)&Pb[(size_t)r * NL + col] = __floats2half2_rn(e0, e1);
            }
            rs += __shfl_xor_sync(0xffffffffu, rs, 1);
            rs += __shfl_xor_sync(0xffffffffu, rs, 2);
            if (qid == 0) {
                atomicAdd(&g_sum[b * NL + r], __expf(mx) * rs);
                if (wn == 0)
                    g_rm[((size_t)(b * NJT + blockIdx.y) * NIT + blockIdx.x) * 128 + (r - j0)] = mx;
            }
        }
}

// ---------------------------------------------------------------------------
// Kernel 4 (fp16 mma): warp tile 64x64, CTA 128(c) x 256(j), 8 warps (2c x 4j),
// 5-stage pipeline, weights pre-folded into P by k_scale.
// out[b][c][j] = x[b][c][j] + g * osc_j * sum_i P[j][i] * Xh[c][i]
// ---------------------------------------------------------------------------
#define OCH 32
#define ONCHK (NL / OCH)            // 64
#define ONSTG 5
#define OROWH 40
#define XROWS 128
#define PROWS 256
#define OSTGH ((XROWS + PROWS) * OROWH)        // halves per stage = 15360
#define SMEM_OUT (ONSTG * OSTGH * 2)           // 153600 B

__global__ __launch_bounds__(256, 1) void k_out_h(const float* __restrict__ x,
                                                  const float* __restrict__ gam,
                                                  float* __restrict__ out) {
    extern __shared__ char smraw[];
    const uint32_t sb = smem_u32(smraw);
    const int tid = threadIdx.x;
    const int b = blockIdx.z;
    const int c0 = blockIdx.y * 128;
    const int j0 = blockIdx.x * 256;
    const __half* xhb = g_Xh + (size_t)b * NC * NL;
    const __half* phb = g_P + (size_t)b * NL * NL;

    auto load_chunk = [&](int n) {
        if (n < ONCHK) {
            const int stg = n % ONSTG;
            const int i0 = n * OCH;
            const uint32_t xbase = sb + (uint32_t)(stg * OSTGH) * 2;
            const uint32_t pbase = xbase + XROWS * OROWH * 2;
#pragma unroll
            for (int u = 0; u < 2; u++) {
                int e = tid + u * 256;
                int r = e >> 2, seg = e & 3;
                cp16(xbase + (r * OROWH + seg * 8) * 2,
                     xhb + (size_t)(c0 + r) * NL + i0 + seg * 8);
            }
#pragma unroll
            for (int u = 0; u < 4; u++) {
                int e = tid + u * 256;
                int r = e >> 2, seg = e & 3;
                cp16(pbase + (r * OROWH + seg * 8) * 2,
                     phb + (size_t)(j0 + r) * NL + i0 + seg * 8);
            }
        }
        asm volatile("cp.async.commit_group;\n" ::: "memory");
    };

    const int wid = tid >> 5, lane = tid & 31;
    const int wc = wid & 1;        // c block: wc*64
    const int wj = wid >> 1;       // j block: wj*64 (4 blocks cover 256)
    const int grp = lane >> 2, qid = lane & 3;
    const int rowA = (lane & 7) + ((lane >> 3) & 1) * 8;
    const int colA = (lane >> 4) * 8;
    const int rowB = (lane & 7) + (lane >> 4) * 8;
    const int colB = ((lane >> 3) & 1) * 8;

    float acc[4][8][4];
#pragma unroll
    for (int mt = 0; mt < 4; mt++)
#pragma unroll
        for (int nt = 0; nt < 8; nt++)
#pragma unroll
            for (int q = 0; q < 4; q++) acc[mt][nt][q] = 0.f;

    auto compute_chunk = [&](int n) {
        const uint32_t xsb = sb + (uint32_t)((n % ONSTG) * OSTGH) * 2;
        const uint32_t psb = xsb + XROWS * OROWH * 2;
#pragma unroll
        for (int kh16 = 0; kh16 < 2; kh16++) {
            const int k = kh16 * 16;
            uint32_t a[4][4];
#pragma unroll
            for (int mt = 0; mt < 4; mt++)
                ldm4(a[mt], xsb + ((wc * 64 + mt * 16 + rowA) * OROWH + k + colA) * 2);
#pragma unroll
            for (int p = 0; p < 4; p++) {
                uint32_t b4[4];
                ldm4(b4, psb + ((wj * 64 + p * 16 + rowB) * OROWH + k + colB) * 2);
#pragma unroll
                for (int mt = 0; mt < 4; mt++) {
                    MMA_F16(acc[mt][2 * p], a[mt], b4[0], b4[1]);
                    MMA_F16(acc[mt][2 * p + 1], a[mt], b4[2], b4[3]);
                }
            }
        }
    };

    load_chunk(0);
    load_chunk(1);
    load_chunk(2);

    for (int g = 0; g < ONCHK / 2; g++) {
        asm volatile("cp.async.wait_group 1;\n" ::: "memory");
        __syncthreads();
        load_chunk(2 * g + 3);
        compute_chunk(2 * g);
        load_chunk(2 * g + 4);
        compute_chunk(2 * g + 1);
    }

    const float g = *gam;
    const float* xb = x + (size_t)b * NC * NL;
    float* ob = out + (size_t)b * NC * NL;
    float2 rv[8];
#pragma unroll
    for (int nt = 0; nt < 8; nt++)
        rv[nt] = *(const float2*)&g_osc[b * NL + j0 + wj * 64 + nt * 8 + qid * 2];

#pragma unroll
    for (int mt = 0; mt < 4; mt++) {
        const int c = c0 + wc * 64 + mt * 16 + grp;
#pragma unroll
        for (int nt = 0; nt < 8; nt++) {
            const int j = j0 + wj * 64 + nt * 8 + qid * 2;
            {
                const size_t o = (size_t)c * NL + j;
                float2 xv = *(const float2*)(xb + o);
                float2 r = make_float2(xv.x + g * rv[nt].x * acc[mt][nt][0],
                                       xv.y + g * rv[nt].y * acc[mt][nt][1]);
                *(float2*)(ob + o) = r;
            }
            {
                const size_t o = (size_t)(c + 8) * NL + j;
                float2 xv = *(const float2*)(xb + o);
                float2 r = make_float2(xv.x + g * rv[nt].x * acc[mt][nt][2],
                                       xv.y + g * rv[nt].y * acc[mt][nt][3]);
                *(float2*)(ob + o) = r;
            }
        }
    }
}

// ---------------------------------------------------------------------------
extern "C" void kernel_launch(void* const* d_in, const int* in_sizes, int n_in,
                              void* d_out, int out_size) {
    (void)in_sizes; (void)n_in; (void)out_size;
    const float* x   = (const float*)d_in[0];
    const float* W1  = (const float*)d_in[1];
    const float* W2  = (const float*)d_in[2];
    const float* gam = (const float*)d_in[3];
    float* out = (float*)d_out;

    cudaFuncSetAttribute(k_proj_mma, cudaFuncAttributeMaxDynamicSharedMemorySize, SMEM_PROJ);
    cudaFuncSetAttribute(k_scores_mma, cudaFuncAttributeMaxDynamicSharedMemorySize, SMEM_SC);
    cudaFuncSetAttribute(k_out_h, cudaFuncAttributeMaxDynamicSharedMemorySize, SMEM_OUT);

    k_zero      <<<NB * NL / 1024, 1024>>>();
    k_proj_mma  <<<dim3(NL / 64, NB), 256, SMEM_PROJ>>>(x, W1, W2);
    k_half      <<<(NB * NC * NL) / (256 * 8), 256>>>(x);
    k_scores_mma<<<dim3(NIT, NJT, NB), 256, SMEM_SC>>>();
    k_prep      <<<NB * NJT, 128>>>();
    k_scale     <<<NB * NL, 256>>>();
    k_out_h     <<<dim3(NL / 256, NC / 128, NB), 256, SMEM_OUT>>>(x, gam, out);
}

// round 14
// speedup vs baseline: 1.0419x; 1.0419x over previous
#include <cuda_runtime.h>
#include <cuda_fp16.h>
#include <cstdint>

#define NB 8
#define NC 512
#define NL 2048
#define NT 64
#define NJT (NL / 128)   // 16 j-tiles
#define NIT (NL / 128)   // 16 i-tiles

// Scratch (static device globals — no allocation in kernel_launch)
__device__ __half g_Qh[NB * NL * NT];
__device__ __half g_Ql[NB * NL * NT];
__device__ __half g_Kh[NB * NL * NT];
__device__ __half g_Kl[NB * NL * NT];
__device__ __half g_P[(size_t)NB * NL * NL];     // P' = exp(s - m_row,tile) fp16  64 MB
__device__ __half g_Xh[(size_t)NB * NC * NL];    // x fp16 (written by k_proj)     16 MB
__device__ float  g_sum[NB * NL];                // exact row sums of e^s
__device__ float  g_rm[NB * NJT * NIT * 128];    // per-(row, i-tile) max

__device__ __forceinline__ uint32_t smem_u32(const void* p) {
    uint32_t r;
    asm("{ .reg .u64 t; cvta.to.shared.u64 t, %1; cvt.u32.u64 %0, t; }" : "=r"(r) : "l"(p));
    return r;
}
__device__ __forceinline__ void cp16(uint32_t dst, const void* src) {
    asm volatile("cp.async.cg.shared.global [%0], [%1], 16;\n" :: "r"(dst), "l"(src));
}
__device__ __forceinline__ void ldm4(uint32_t* r, uint32_t addr) {
    asm volatile("ldmatrix.sync.aligned.m8n8.x4.shared.b16 {%0,%1,%2,%3}, [%4];"
                 : "=r"(r[0]), "=r"(r[1]), "=r"(r[2]), "=r"(r[3]) : "r"(addr));
}

#define MMA_F16(ac, A, b0v, b1v)                                              \
    asm volatile("mma.sync.aligned.m16n8k16.row.col.f32.f16.f16.f32 "         \
                 "{%0,%1,%2,%3}, {%4,%5,%6,%7}, {%8,%9}, {%0,%1,%2,%3};"      \
                 : "+f"(ac[0]), "+f"(ac[1]), "+f"(ac[2]), "+f"(ac[3])         \
                 : "r"(A[0]), "r"(A[1]), "r"(A[2]), "r"(A[3]),                \
                   "r"(b0v), "r"(b1v));

// ---------------------------------------------------------------------------
__global__ void k_zero() { g_sum[blockIdx.x * 1024 + threadIdx.x] = 0.f; }

// ---------------------------------------------------------------------------
// Kernel 1 (fp16 hi/lo 3-term MMA): Q/K projection + fused x->fp16 emit.
// ---------------------------------------------------------------------------
#define PXROW 72
#define P_XH 0
#define P_XL (64 * PXROW)
#define P_WH (2 * 64 * PXROW)
#define P_WL (2 * 64 * PXROW + 128 * PXROW)
#define SMEM_PROJ ((2 * 64 * PXROW + 2 * 128 * PXROW) * 2)   // 55296 B

__global__ __launch_bounds__(256, 2) void k_proj_mma(const float* __restrict__ x,
                                                     const float* __restrict__ W1,
                                                     const float* __restrict__ W2) {
    extern __shared__ __half smh[];
    const uint32_t sb = smem_u32(smh);
    const int tid = threadIdx.x;
    const int b = blockIdx.y;
    const int l0 = blockIdx.x * 64;
    const float* xb = x + (size_t)b * NC * NL;

    const int wid = tid >> 5, lane = tid & 31;
    const int wm = wid & 1;
    const int wn = wid >> 1;
    const int grp = lane >> 2, qid = lane & 3;
    const int rowA = (lane & 7) + ((lane >> 3) & 1) * 8;
    const int colA = (lane >> 4) * 8;
    const int rowB = (lane & 7) + (lane >> 4) * 8;
    const int colB = ((lane >> 3) & 1) * 8;

    float acc[2][4][4];
#pragma unroll
    for (int mt = 0; mt < 2; mt++)
#pragma unroll
        for (int nt = 0; nt < 4; nt++)
#pragma unroll
            for (int q = 0; q < 4; q++) acc[mt][nt][q] = 0.f;

    for (int ch = 0; ch < NC / 64; ch++) {
        const int c0 = ch * 64;
#pragma unroll
        for (int u = 0; u < 4; u++) {
            int f = tid + u * 256;
            int c = f & 63, lq = f >> 6;
            float4 v = *(const float4*)(xb + (size_t)(c0 + c) * NL + l0 + lq * 4);
            float vv[4] = {v.x, v.y, v.z, v.w};
            __half hx[4];
#pragma unroll
            for (int j = 0; j < 4; j++) {
                __half h = __float2half_rn(vv[j]);
                __half l = __float2half_rn(vv[j] - __half2float(h));
                smh[P_XH + (lq * 4 + j) * PXROW + c] = h;
                smh[P_XL + (lq * 4 + j) * PXROW + c] = l;
                hx[j] = h;
            }
            // fused x -> fp16 emit (same rounding as the old k_half)
            *(uint2*)&g_Xh[((size_t)b * NC + c0 + c) * NL + l0 + lq * 4] = *(uint2*)hx;
        }
#pragma unroll
        for (int u = 0; u < 8; u++) {
            int f = tid + u * 256;
            int t = f & 127, cq = f >> 7;
            const float* wsrc = (t < 64) ? (W1 + t * NC) : (W2 + (t - 64) * NC);
            float4 v = *(const float4*)(wsrc + c0 + cq * 4);
            float vv[4] = {v.x, v.y, v.z, v.w};
            __half hh[4], hl[4];
#pragma unroll
            for (int j = 0; j < 4; j++) {
                hh[j] = __float2half_rn(vv[j]);
                hl[j] = __float2half_rn(vv[j] - __half2float(hh[j]));
            }
            *(uint2*)&smh[P_WH + t * PXROW + cq * 4] = *(uint2*)hh;
            *(uint2*)&smh[P_WL + t * PXROW + cq * 4] = *(uint2*)hl;
        }
        __syncthreads();

#pragma unroll
        for (int k16 = 0; k16 < 4; k16++) {
            const int k = k16 * 16;
            uint32_t ah[2][4], al[2][4];
#pragma unroll
            for (int mt = 0; mt < 2; mt++) {
                const uint32_t ao = ((wm * 32 + mt * 16 + rowA) * PXROW + k + colA) * 2;
                ldm4(ah[mt], sb + P_XH * 2 + ao);
                ldm4(al[mt], sb + P_XL * 2 + ao);
            }
#pragma unroll
            for (int p = 0; p < 2; p++) {
                const uint32_t bo = ((wn * 32 + p * 16 + rowB) * PXROW + k + colB) * 2;
                uint32_t bh[4], bl[4];
                ldm4(bh, sb + P_WH * 2 + bo);
                ldm4(bl, sb + P_WL * 2 + bo);
#pragma unroll
                for (int e = 0; e < 2; e++) {
                    const int nt = p * 2 + e;
#pragma unroll
                    for (int mt = 0; mt < 2; mt++) {
                        MMA_F16(acc[mt][nt], ah[mt], bh[2 * e], bh[2 * e + 1]);
                        MMA_F16(acc[mt][nt], ah[mt], bl[2 * e], bl[2 * e + 1]);
                        MMA_F16(acc[mt][nt], al[mt], bh[2 * e], bh[2 * e + 1]);
                    }
                }
            }
        }
        __syncthreads();
    }

#pragma unroll
    for (int mt = 0; mt < 2; mt++) {
#pragma unroll
        for (int nt = 0; nt < 4; nt++) {
            const int t = wn * 32 + nt * 8 + qid * 2;
#pragma unroll
            for (int hrow = 0; hrow < 2; hrow++) {
                const int l = l0 + wm * 32 + mt * 16 + grp + hrow * 8;
                float v0 = acc[mt][nt][hrow * 2 + 0];
                float v1 = acc[mt][nt][hrow * 2 + 1];
                __half h0 = __float2half_rn(v0), h1 = __float2half_rn(v1);
                __half l0h = __float2half_rn(v0 - __half2float(h0));
                __half l1h = __float2half_rn(v1 - __half2float(h1));
                __half hp[2] = {h0, h1}, lp[2] = {l0h, l1h};
                const size_t off = ((size_t)b * NL + l) * NT + (t & 63);
                if (t < 64) {
                    *(uint32_t*)&g_Qh[off] = *(uint32_t*)hp;
                    *(uint32_t*)&g_Ql[off] = *(uint32_t*)lp;
                } else {
                    *(uint32_t*)&g_Kh[off] = *(uint32_t*)hp;
                    *(uint32_t*)&g_Kl[off] = *(uint32_t*)lp;
                }
            }
        }
    }
}

// ---------------------------------------------------------------------------
// Kernel 2 (fp16 hi/lo 3-term mma): P' = exp(s - m_row,tile) fp16,
// m_rt -> g_rm, exact row sums -> atomicAdd. Two-group staged tile load.
// ---------------------------------------------------------------------------
#define SROWH 72
#define STILE_H (128 * SROWH)
#define SMEM_SC (4 * STILE_H * 2)   // 73728 B

__global__ __launch_bounds__(256) void k_scores_mma() {
    extern __shared__ char smraw[];
    const uint32_t sb = smem_u32(smraw);
    const int tid = threadIdx.x;
    const int b = blockIdx.z;
    const int j0 = blockIdx.y * 128;
    const int i0 = blockIdx.x * 128;

    const __half* srcs[4] = {g_Qh + ((size_t)b * NL + j0) * NT,
                             g_Ql + ((size_t)b * NL + j0) * NT,
                             g_Kh + ((size_t)b * NL + i0) * NT,
                             g_Kl + ((size_t)b * NL + i0) * NT};
#pragma unroll
    for (int t = 0; t < 4; t++) {
#pragma unroll
        for (int u = 0; u < 2; u++) {
            int e = tid + u * 256;
            int r = e >> 2, seg = e & 3;
            cp16(sb + (t * STILE_H + r * SROWH + seg * 8) * 2,
                 srcs[t] + (size_t)r * NT + seg * 8);
        }
    }
    asm volatile("cp.async.commit_group;\n" ::: "memory");
#pragma unroll
    for (int t = 0; t < 4; t++) {
#pragma unroll
        for (int u = 0; u < 2; u++) {
            int e = tid + u * 256;
            int r = e >> 2, seg = 4 + (e & 3);
            cp16(sb + (t * STILE_H + r * SROWH + seg * 8) * 2,
                 srcs[t] + (size_t)r * NT + seg * 8);
        }
    }
    asm volatile("cp.async.commit_group;\n" ::: "memory");

    const int wid = tid >> 5, lane = tid & 31;
    const int wm = wid & 3;
    const int wn = wid >> 2;
    const int grp = lane >> 2, qid = lane & 3;
    const int rowA = (lane & 7) + ((lane >> 3) & 1) * 8;
    const int colA = (lane >> 4) * 8;
    const int rowB = (lane & 7) + (lane >> 4) * 8;
    const int colB = ((lane >> 3) & 1) * 8;

    const uint32_t qh_b = sb;
    const uint32_t ql_b = sb + STILE_H * 2;
    const uint32_t kh_b = sb + 2 * STILE_H * 2;
    const uint32_t kl_b = sb + 3 * STILE_H * 2;

    float acc[2][8][4];
#pragma unroll
    for (int mt = 0; mt < 2; mt++)
#pragma unroll
        for (int nt = 0; nt < 8; nt++)
#pragma unroll
            for (int q = 0; q < 4; q++) acc[mt][nt][q] = 0.f;

    auto compute_k16 = [&](int kh16) {
        const int k = kh16 * 16;
        uint32_t ah[2][4], al[2][4];
#pragma unroll
        for (int mt = 0; mt < 2; mt++) {
            const uint32_t ao = ((wm * 32 + mt * 16 + rowA) * SROWH + k + colA) * 2;
            ldm4(ah[mt], qh_b + ao);
            ldm4(al[mt], ql_b + ao);
        }
#pragma unroll
        for (int p = 0; p < 4; p++) {
            const uint32_t bo = ((wn * 64 + p * 16 + rowB) * SROWH + k + colB) * 2;
            uint32_t bh[4], bl[4];
            ldm4(bh, kh_b + bo);
            ldm4(bl, kl_b + bo);
#pragma unroll
            for (int e = 0; e < 2; e++) {
                const int nt = p * 2 + e;
#pragma unroll
                for (int mt = 0; mt < 2; mt++) {
                    MMA_F16(acc[mt][nt], ah[mt], bh[2 * e], bh[2 * e + 1]);
                    MMA_F16(acc[mt][nt], ah[mt], bl[2 * e], bl[2 * e + 1]);
                    MMA_F16(acc[mt][nt], al[mt], bh[2 * e], bh[2 * e + 1]);
                }
            }
        }
    };

    asm volatile("cp.async.wait_group 1;\n" ::: "memory");
    __syncthreads();
    compute_k16(0);
    compute_k16(1);
    asm volatile("cp.async.wait_group 0;\n" ::: "memory");
    __syncthreads();
    compute_k16(2);
    compute_k16(3);

    // per-row (within tile) max: quad reduce, then combine the 2 wn warps
    float lmax[2][2];
#pragma unroll
    for (int mt = 0; mt < 2; mt++)
#pragma unroll
        for (int h = 0; h < 2; h++) {
            float m = -1e30f;
#pragma unroll
            for (int nt = 0; nt < 8; nt++)
                m = fmaxf(m, fmaxf(acc[mt][nt][2 * h], acc[mt][nt][2 * h + 1]));
            m = fmaxf(m, __shfl_xor_sync(0xffffffffu, m, 1));
            m = fmaxf(m, __shfl_xor_sync(0xffffffffu, m, 2));
            lmax[mt][h] = m;
        }
    float* red = (float*)smraw;
    __syncthreads();
    if (qid == 0) {
#pragma unroll
        for (int mt = 0; mt < 2; mt++)
#pragma unroll
            for (int h = 0; h < 2; h++)
                red[(((wn * 4 + wm) * 2 + mt) * 2 + h) * 8 + grp] = lmax[mt][h];
    }
    __syncthreads();

    __half* Pb = g_P + (size_t)b * NL * NL;
#pragma unroll
    for (int mt = 0; mt < 2; mt++)
#pragma unroll
        for (int h = 0; h < 2; h++) {
            const float mx = fmaxf(lmax[mt][h],
                red[((((1 - wn) * 4 + wm) * 2 + mt) * 2 + h) * 8 + grp]);
            const int r = j0 + wm * 32 + mt * 16 + grp + h * 8;
            float rs = 0.f;
#pragma unroll
            for (int nt = 0; nt < 8; nt++) {
                const int col = i0 + wn * 64 + nt * 8 + qid * 2;
                float e0 = __expf(acc[mt][nt][2 * h] - mx);
                float e1 = __expf(acc[mt][nt][2 * h + 1] - mx);
                rs += e0 + e1;
                *(__half2*)&Pb[(size_t)r * NL + col] = __floats2half2_rn(e0, e1);
            }
            rs += __shfl_xor_sync(0xffffffffu, rs, 1);
            rs += __shfl_xor_sync(0xffffffffu, rs, 2);
            if (qid == 0) {
                atomicAdd(&g_sum[b * NL + r], __expf(mx) * rs);
                if (wn == 0)
                    g_rm[((size_t)(b * NJT + blockIdx.y) * NIT + blockIdx.x) * 128 + (r - j0)] = mx;
            }
        }
}

// ---------------------------------------------------------------------------
// Kernel 3 (fp16 mma, 5-stage pipeline, prep fused in-kernel):
// out[b][c][j] = x[b][c][j] + g * osc_j * sum_it w(j,it) sum_{i in it} P' X
// ---------------------------------------------------------------------------
#define ICH 32
#define NCHK (NL / ICH)             // 64
#define NSTG 5
#define ROWH 40
#define HTILE (128 * ROWH)
#define HSTG (2 * HTILE)
#define SMEM_OUT (NSTG * HSTG * 2)  // 102400 B

__global__ __launch_bounds__(256, 2) void k_out_h(const float* __restrict__ x,
                                                  const float* __restrict__ gam,
                                                  float* __restrict__ out) {
    extern __shared__ char smraw[];
    __shared__ float ws2[NIT][128];
    __shared__ float osc_s[128];
    const uint32_t sb = smem_u32(smraw);
    const int tid = threadIdx.x;
    const int b = blockIdx.z;
    const int c0 = blockIdx.y * 128;
    const int j0 = blockIdx.x * 128;
    const __half* xhb = g_Xh + (size_t)b * NC * NL;
    const __half* phb = g_P + (size_t)b * NL * NL;

    // in-kernel prep: per-row C_j, per-(row, i-tile) weights, output scale
    if (tid < 128) {
        const size_t base = (size_t)(b * NJT + blockIdx.x) * NIT * 128 + tid;
        float mv[NIT];
        float C = -1e30f;
#pragma unroll
        for (int it = 0; it < NIT; it++) {
            mv[it] = g_rm[base + it * 128];
            C = fmaxf(C, mv[it]);
        }
#pragma unroll
        for (int it = 0; it < NIT; it++)
            ws2[it][tid] = __expf(mv[it] - C);
        osc_s[tid] = __expf(C) / g_sum[b * NL + j0 + tid];
    }

    auto load_chunk = [&](int n) {
        if (n < NCHK) {
            const int stg = n % NSTG;
            const int i0 = n * ICH;
            const uint32_t xbase = sb + (uint32_t)(stg * HSTG) * 2;
            const uint32_t pbase = xbase + HTILE * 2;
#pragma unroll
            for (int u = 0; u < 2; u++) {
                int e = tid + u * 256;
                int r = e >> 2, seg = e & 3;
                cp16(xbase + (r * ROWH + seg * 8) * 2, xhb + (size_t)(c0 + r) * NL + i0 + seg * 8);
            }
#pragma unroll
            for (int u = 0; u < 2; u++) {
                int e = tid + u * 256;
                int r = e >> 2, seg = e & 3;
                cp16(pbase + (r * ROWH + seg * 8) * 2, phb + (size_t)(j0 + r) * NL + i0 + seg * 8);
            }
        }
        asm volatile("cp.async.commit_group;\n" ::: "memory");
    };

    const int wid = tid >> 5, lane = tid & 31;
    const int wm = wid & 3;
    const int wn = wid >> 2;
    const int grp = lane >> 2, qid = lane & 3;
    const int rowA = (lane & 7) + ((lane >> 3) & 1) * 8;
    const int colA = (lane >> 4) * 8;
    const int rowB = (lane & 7) + (lane >> 4) * 8;
    const int colB = ((lane >> 3) & 1) * 8;

    float acc[2][8][4];
#pragma unroll
    for (int mt = 0; mt < 2; mt++)
#pragma unroll
        for (int nt = 0; nt < 8; nt++)
#pragma unroll
            for (int q = 0; q < 4; q++) acc[mt][nt][q] = 0.f;

    __half2 wha[4], whb[4];

    auto compute_chunk = [&](int n) {
        const uint32_t xsb = sb + (uint32_t)((n % NSTG) * HSTG) * 2;
        const uint32_t psb = xsb + HTILE * 2;
#pragma unroll
        for (int kh16 = 0; kh16 < 2; kh16++) {
            const int k = kh16 * 16;
            uint32_t a[2][4];
#pragma unroll
            for (int mt = 0; mt < 2; mt++)
                ldm4(a[mt], xsb + ((wm * 32 + mt * 16 + rowA) * ROWH + k + colA) * 2);
#pragma unroll
            for (int p = 0; p < 4; p++) {
                uint32_t b4[4];
                ldm4(b4, psb + ((wn * 64 + p * 16 + rowB) * ROWH + k + colB) * 2);
                {
                    __half2 t0 = __hmul2(*(__half2*)&b4[0], wha[p]);
                    __half2 t1 = __hmul2(*(__half2*)&b4[1], wha[p]);
                    __half2 t2 = __hmul2(*(__half2*)&b4[2], whb[p]);
                    __half2 t3 = __hmul2(*(__half2*)&b4[3], whb[p]);
                    b4[0] = *(uint32_t*)&t0; b4[1] = *(uint32_t*)&t1;
                    b4[2] = *(uint32_t*)&t2; b4[3] = *(uint32_t*)&t3;
                }
                MMA_F16(acc[0][2 * p], a[0], b4[0], b4[1]);
                MMA_F16(acc[1][2 * p], a[1], b4[0], b4[1]);
                MMA_F16(acc[0][2 * p + 1], a[0], b4[2], b4[3]);
                MMA_F16(acc[1][2 * p + 1], a[1], b4[2], b4[3]);
            }
        }
    };

    load_chunk(0);
    load_chunk(1);
    load_chunk(2);

    for (int g = 0; g < NCHK / 2; g++) {
        asm volatile("cp.async.wait_group 1;\n" ::: "memory");
        __syncthreads();

        if ((g & 1) == 0) {      // new i-tile: refresh per-row weights
            const int it = g >> 1;
#pragma unroll
            for (int p = 0; p < 4; p++) {
                wha[p] = __float2half2_rn(ws2[it][wn * 64 + p * 16 + grp]);
                whb[p] = __float2half2_rn(ws2[it][wn * 64 + p * 16 + grp + 8]);
            }
        }

        load_chunk(2 * g + 3);
        compute_chunk(2 * g);
        load_chunk(2 * g + 4);
        compute_chunk(2 * g + 1);
    }

    const float g = *gam;
    const float* xb = x + (size_t)b * NC * NL;
    float* ob = out + (size_t)b * NC * NL;
    float2 rv[8];
#pragma unroll
    for (int nt = 0; nt < 8; nt++) {
        const int jl = wn * 64 + nt * 8 + qid * 2;
        rv[nt] = make_float2(osc_s[jl], osc_s[jl + 1]);
    }

#pragma unroll
    for (int mt = 0; mt < 2; mt++) {
        const int c = c0 + wm * 32 + mt * 16 + grp;
#pragma unroll
        for (int nt = 0; nt < 8; nt++) {
            const int j = j0 + wn * 64 + nt * 8 + qid * 2;
            {
                const size_t o = (size_t)c * NL + j;
                float2 xv = *(const float2*)(xb + o);
                float2 r = make_float2(xv.x + g * rv[nt].x * acc[mt][nt][0],
                                       xv.y + g * rv[nt].y * acc[mt][nt][1]);
                *(float2*)(ob + o) = r;
            }
            {
                const size_t o = (size_t)(c + 8) * NL + j;
                float2 xv = *(const float2*)(xb + o);
                float2 r = make_float2(xv.x + g * rv[nt].x * acc[mt][nt][2],
                                       xv.y + g * rv[nt].y * acc[mt][nt][3]);
                *(float2*)(ob + o) = r;
            }
        }
    }
}

// ---------------------------------------------------------------------------
extern "C" void kernel_launch(void* const* d_in, const int* in_sizes, int n_in,
                              void* d_out, int out_size) {
    (void)in_sizes; (void)n_in; (void)out_size;
    const float* x   = (const float*)d_in[0];
    const float* W1  = (const float*)d_in[1];
    const float* W2  = (const float*)d_in[2];
    const float* gam = (const float*)d_in[3];
    float* out = (float*)d_out;

    cudaFuncSetAttribute(k_proj_mma, cudaFuncAttributeMaxDynamicSharedMemorySize, SMEM_PROJ);
    cudaFuncSetAttribute(k_scores_mma, cudaFuncAttributeMaxDynamicSharedMemorySize, SMEM_SC);
    cudaFuncSetAttribute(k_out_h, cudaFuncAttributeMaxDynamicSharedMemorySize, SMEM_OUT);

    k_zero      <<<NB * NL / 1024, 1024>>>();
    k_proj_mma  <<<dim3(NL / 64, NB), 256, SMEM_PROJ>>>(x, W1, W2);
    k_scores_mma<<<dim3(NIT, NJT, NB), 256, SMEM_SC>>>();
    k_out_h     <<<dim3(NL / 128, NC / 128, NB), 256, SMEM_OUT>>>(x, gam, out);
}

// round 15
// speedup vs baseline: 1.2043x; 1.1559x over previous
#include <cuda_runtime.h>
#include <cuda_fp16.h>
#include <cstdint>

#define NB 8
#define NC 512
#define NL 2048
#define NT 64
#define NJT (NL / 128)   // 16 j-tiles
#define NIT (NL / 128)   // 16 i-tiles

// Scratch (static device globals — no allocation in kernel_launch)
__device__ __half g_Qh[NB * NL * NT];
__device__ __half g_Ql[NB * NL * NT];
__device__ __half g_Kh[NB * NL * NT];
__device__ __half g_Kl[NB * NL * NT];
__device__ __half g_P[(size_t)NB * NL * NL];     // P' = exp(s - m_row,tile) fp16  64 MB
__device__ __half g_Xh[(size_t)NB * NC * NL];    // x fp16 (written by k_proj)     16 MB
__device__ float  g_sum[NB * NL];                // exact row sums of e^s
__device__ float  g_rm[NB * NJT * NIT * 128];    // per-(row, i-tile) max

__device__ __forceinline__ uint32_t smem_u32(const void* p) {
    uint32_t r;
    asm("{ .reg .u64 t; cvta.to.shared.u64 t, %1; cvt.u32.u64 %0, t; }" : "=r"(r) : "l"(p));
    return r;
}
__device__ __forceinline__ void cp16(uint32_t dst, const void* src) {
    asm volatile("cp.async.cg.shared.global [%0], [%1], 16;\n" :: "r"(dst), "l"(src));
}
__device__ __forceinline__ void ldm4(uint32_t* r, uint32_t addr) {
    asm volatile("ldmatrix.sync.aligned.m8n8.x4.shared.b16 {%0,%1,%2,%3}, [%4];"
                 : "=r"(r[0]), "=r"(r[1]), "=r"(r[2]), "=r"(r[3]) : "r"(addr));
}
__device__ __forceinline__ void ldm4t(uint32_t* r, uint32_t addr) {
    asm volatile("ldmatrix.sync.aligned.m8n8.x4.trans.shared.b16 {%0,%1,%2,%3}, [%4];"
                 : "=r"(r[0]), "=r"(r[1]), "=r"(r[2]), "=r"(r[3]) : "r"(addr));
}

#define MMA_F16(ac, A, b0v, b1v)                                              \
    asm volatile("mma.sync.aligned.m16n8k16.row.col.f32.f16.f16.f32 "         \
                 "{%0,%1,%2,%3}, {%4,%5,%6,%7}, {%8,%9}, {%0,%1,%2,%3};"      \
                 : "+f"(ac[0]), "+f"(ac[1]), "+f"(ac[2]), "+f"(ac[3])         \
                 : "r"(A[0]), "r"(A[1]), "r"(A[2]), "r"(A[3]),                \
                   "r"(b0v), "r"(b1v));

// ---------------------------------------------------------------------------
__global__ void k_zero() { g_sum[blockIdx.x * 1024 + threadIdx.x] = 0.f; }

// ---------------------------------------------------------------------------
// Kernel 1 (fp16 hi/lo 3-term MMA): Q/K projection + fused x->fp16 emit.
// x tiles stored [c][l] (natural layout, vectorized stores); A fragments
// loaded via ldmatrix.trans (transpose in HW). W tiles [t][c] as before.
// ---------------------------------------------------------------------------
#define PXROW 72
#define P_XH 0
#define P_XL (64 * PXROW)
#define P_WH (2 * 64 * PXROW)
#define P_WL (2 * 64 * PXROW + 128 * PXROW)
#define SMEM_PROJ ((2 * 64 * PXROW + 2 * 128 * PXROW) * 2)   // 55296 B

__global__ __launch_bounds__(256, 2) void k_proj_mma(const float* __restrict__ x,
                                                     const float* __restrict__ W1,
                                                     const float* __restrict__ W2) {
    extern __shared__ __half smh[];
    const uint32_t sb = smem_u32(smh);
    const int tid = threadIdx.x;
    const int b = blockIdx.y;
    const int l0 = blockIdx.x * 64;
    const float* xb = x + (size_t)b * NC * NL;

    const int wid = tid >> 5, lane = tid & 31;
    const int wm = wid & 1;
    const int wn = wid >> 1;
    const int grp = lane >> 2, qid = lane & 3;
    // A via ldmatrix.trans from [c][l] storage: row = k(c) offset, col = m(l) offset
    const int rowT = (lane & 7) + ((lane >> 4) & 1) * 8;
    const int colT = ((lane >> 3) & 1) * 8;
    // B (W) via non-trans from [t][c] storage
    const int rowB = (lane & 7) + (lane >> 4) * 8;
    const int colB = ((lane >> 3) & 1) * 8;

    float acc[2][4][4];
#pragma unroll
    for (int mt = 0; mt < 2; mt++)
#pragma unroll
        for (int nt = 0; nt < 4; nt++)
#pragma unroll
            for (int q = 0; q < 4; q++) acc[mt][nt][q] = 0.f;

    for (int ch = 0; ch < NC / 64; ch++) {
        const int c0 = ch * 64;
        // --- x tile [64c][64l]: natural layout, hi/lo split, vectorized stores
#pragma unroll
        for (int u = 0; u < 4; u++) {
            int f = tid + u * 256;
            int c = f >> 4, lq = f & 15;   // 16 threads cover one 256B c-row
            float4 v = *(const float4*)(xb + (size_t)(c0 + c) * NL + l0 + lq * 4);
            float vv[4] = {v.x, v.y, v.z, v.w};
            __half hh[4], hl[4];
#pragma unroll
            for (int j = 0; j < 4; j++) {
                hh[j] = __float2half_rn(vv[j]);
                hl[j] = __float2half_rn(vv[j] - __half2float(hh[j]));
            }
            *(uint2*)&smh[P_XH + c * PXROW + lq * 4] = *(uint2*)hh;
            *(uint2*)&smh[P_XL + c * PXROW + lq * 4] = *(uint2*)hl;
            *(uint2*)&g_Xh[((size_t)b * NC + c0 + c) * NL + l0 + lq * 4] = *(uint2*)hh;
        }
        // --- W tile [128t][64c]
#pragma unroll
        for (int u = 0; u < 8; u++) {
            int f = tid + u * 256;
            int t = f >> 4, cq = f & 15;
            const float* wsrc = (t < 64) ? (W1 + t * NC) : (W2 + (t - 64) * NC);
            float4 v = *(const float4*)(wsrc + c0 + cq * 4);
            float vv[4] = {v.x, v.y, v.z, v.w};
            __half hh[4], hl[4];
#pragma unroll
            for (int j = 0; j < 4; j++) {
                hh[j] = __float2half_rn(vv[j]);
                hl[j] = __float2half_rn(vv[j] - __half2float(hh[j]));
            }
            *(uint2*)&smh[P_WH + t * PXROW + cq * 4] = *(uint2*)hh;
            *(uint2*)&smh[P_WL + t * PXROW + cq * 4] = *(uint2*)hl;
        }
        __syncthreads();

#pragma unroll
        for (int k16 = 0; k16 < 4; k16++) {
            const int k = k16 * 16;
            uint32_t ah[2][4], al[2][4];
#pragma unroll
            for (int mt = 0; mt < 2; mt++) {
                const uint32_t ao = ((k + rowT) * PXROW + wm * 32 + mt * 16 + colT) * 2;
                ldm4t(ah[mt], sb + P_XH * 2 + ao);
                ldm4t(al[mt], sb + P_XL * 2 + ao);
            }
#pragma unroll
            for (int p = 0; p < 2; p++) {
                const uint32_t bo = ((wn * 32 + p * 16 + rowB) * PXROW + k + colB) * 2;
                uint32_t bh[4], bl[4];
                ldm4(bh, sb + P_WH * 2 + bo);
                ldm4(bl, sb + P_WL * 2 + bo);
#pragma unroll
                for (int e = 0; e < 2; e++) {
                    const int nt = p * 2 + e;
#pragma unroll
                    for (int mt = 0; mt < 2; mt++) {
                        MMA_F16(acc[mt][nt], ah[mt], bh[2 * e], bh[2 * e + 1]);
                        MMA_F16(acc[mt][nt], ah[mt], bl[2 * e], bl[2 * e + 1]);
                        MMA_F16(acc[mt][nt], al[mt], bh[2 * e], bh[2 * e + 1]);
                    }
                }
            }
        }
        __syncthreads();
    }

#pragma unroll
    for (int mt = 0; mt < 2; mt++) {
#pragma unroll
        for (int nt = 0; nt < 4; nt++) {
            const int t = wn * 32 + nt * 8 + qid * 2;
#pragma unroll
            for (int hrow = 0; hrow < 2; hrow++) {
                const int l = l0 + wm * 32 + mt * 16 + grp + hrow * 8;
                float v0 = acc[mt][nt][hrow * 2 + 0];
                float v1 = acc[mt][nt][hrow * 2 + 1];
                __half h0 = __float2half_rn(v0), h1 = __float2half_rn(v1);
                __half l0h = __float2half_rn(v0 - __half2float(h0));
                __half l1h = __float2half_rn(v1 - __half2float(h1));
                __half hp[2] = {h0, h1}, lp[2] = {l0h, l1h};
                const size_t off = ((size_t)b * NL + l) * NT + (t & 63);
                if (t < 64) {
                    *(uint32_t*)&g_Qh[off] = *(uint32_t*)hp;
                    *(uint32_t*)&g_Ql[off] = *(uint32_t*)lp;
                } else {
                    *(uint32_t*)&g_Kh[off] = *(uint32_t*)hp;
                    *(uint32_t*)&g_Kl[off] = *(uint32_t*)lp;
                }
            }
        }
    }
}

// ---------------------------------------------------------------------------
// Kernel 2 (fp16 hi/lo 3-term mma): P' = exp(s - m_row,tile) fp16,
// m_rt -> g_rm, exact row sums -> atomicAdd. Two-group staged tile load.
// ---------------------------------------------------------------------------
#define SROWH 72
#define STILE_H (128 * SROWH)
#define SMEM_SC (4 * STILE_H * 2)   // 73728 B

__global__ __launch_bounds__(256) void k_scores_mma() {
    extern __shared__ char smraw[];
    const uint32_t sb = smem_u32(smraw);
    const int tid = threadIdx.x;
    const int b = blockIdx.z;
    const int j0 = blockIdx.y * 128;
    const int i0 = blockIdx.x * 128;

    const __half* srcs[4] = {g_Qh + ((size_t)b * NL + j0) * NT,
                             g_Ql + ((size_t)b * NL + j0) * NT,
                             g_Kh + ((size_t)b * NL + i0) * NT,
                             g_Kl + ((size_t)b * NL + i0) * NT};
#pragma unroll
    for (int t = 0; t < 4; t++) {
#pragma unroll
        for (int u = 0; u < 2; u++) {
            int e = tid + u * 256;
            int r = e >> 2, seg = e & 3;
            cp16(sb + (t * STILE_H + r * SROWH + seg * 8) * 2,
                 srcs[t] + (size_t)r * NT + seg * 8);
        }
    }
    asm volatile("cp.async.commit_group;\n" ::: "memory");
#pragma unroll
    for (int t = 0; t < 4; t++) {
#pragma unroll
        for (int u = 0; u < 2; u++) {
            int e = tid + u * 256;
            int r = e >> 2, seg = 4 + (e & 3);
            cp16(sb + (t * STILE_H + r * SROWH + seg * 8) * 2,
                 srcs[t] + (size_t)r * NT + seg * 8);
        }
    }
    asm volatile("cp.async.commit_group;\n" ::: "memory");

    const int wid = tid >> 5, lane = tid & 31;
    const int wm = wid & 3;
    const int wn = wid >> 2;
    const int grp = lane >> 2, qid = lane & 3;
    const int rowA = (lane & 7) + ((lane >> 3) & 1) * 8;
    const int colA = (lane >> 4) * 8;
    const int rowB = (lane & 7) + (lane >> 4) * 8;
    const int colB = ((lane >> 3) & 1) * 8;

    const uint32_t qh_b = sb;
    const uint32_t ql_b = sb + STILE_H * 2;
    const uint32_t kh_b = sb + 2 * STILE_H * 2;
    const uint32_t kl_b = sb + 3 * STILE_H * 2;

    float acc[2][8][4];
#pragma unroll
    for (int mt = 0; mt < 2; mt++)
#pragma unroll
        for (int nt = 0; nt < 8; nt++)
#pragma unroll
            for (int q = 0; q < 4; q++) acc[mt][nt][q] = 0.f;

    auto compute_k16 = [&](int kh16) {
        const int k = kh16 * 16;
        uint32_t ah[2][4], al[2][4];
#pragma unroll
        for (int mt = 0; mt < 2; mt++) {
            const uint32_t ao = ((wm * 32 + mt * 16 + rowA) * SROWH + k + colA) * 2;
            ldm4(ah[mt], qh_b + ao);
            ldm4(al[mt], ql_b + ao);
        }
#pragma unroll
        for (int p = 0; p < 4; p++) {
            const uint32_t bo = ((wn * 64 + p * 16 + rowB) * SROWH + k + colB) * 2;
            uint32_t bh[4], bl[4];
            ldm4(bh, kh_b + bo);
            ldm4(bl, kl_b + bo);
#pragma unroll
            for (int e = 0; e < 2; e++) {
                const int nt = p * 2 + e;
#pragma unroll
                for (int mt = 0; mt < 2; mt++) {
                    MMA_F16(acc[mt][nt], ah[mt], bh[2 * e], bh[2 * e + 1]);
                    MMA_F16(acc[mt][nt], ah[mt], bl[2 * e], bl[2 * e + 1]);
                    MMA_F16(acc[mt][nt], al[mt], bh[2 * e], bh[2 * e + 1]);
                }
            }
        }
    };

    asm volatile("cp.async.wait_group 1;\n" ::: "memory");
    __syncthreads();
    compute_k16(0);
    compute_k16(1);
    asm volatile("cp.async.wait_group 0;\n" ::: "memory");
    __syncthreads();
    compute_k16(2);
    compute_k16(3);

    // per-row (within tile) max: quad reduce, then combine the 2 wn warps
    float lmax[2][2];
#pragma unroll
    for (int mt = 0; mt < 2; mt++)
#pragma unroll
        for (int h = 0; h < 2; h++) {
            float m = -1e30f;
#pragma unroll
            for (int nt = 0; nt < 8; nt++)
                m = fmaxf(m, fmaxf(acc[mt][nt][2 * h], acc[mt][nt][2 * h + 1]));
            m = fmaxf(m, __shfl_xor_sync(0xffffffffu, m, 1));
            m = fmaxf(m, __shfl_xor_sync(0xffffffffu, m, 2));
            lmax[mt][h] = m;
        }
    float* red = (float*)smraw;
    __syncthreads();
    if (qid == 0) {
#pragma unroll
        for (int mt = 0; mt < 2; mt++)
#pragma unroll
            for (int h = 0; h < 2; h++)
                red[(((wn * 4 + wm) * 2 + mt) * 2 + h) * 8 + grp] = lmax[mt][h];
    }
    __syncthreads();

    __half* Pb = g_P + (size_t)b * NL * NL;
#pragma unroll
    for (int mt = 0; mt < 2; mt++)
#pragma unroll
        for (int h = 0; h < 2; h++) {
            const float mx = fmaxf(lmax[mt][h],
                red[((((1 - wn) * 4 + wm) * 2 + mt) * 2 + h) * 8 + grp]);
            const int r = j0 + wm * 32 + mt * 16 + grp + h * 8;
            float rs = 0.f;
#pragma unroll
            for (int nt = 0; nt < 8; nt++) {
                const int col = i0 + wn * 64 + nt * 8 + qid * 2;
                float e0 = __expf(acc[mt][nt][2 * h] - mx);
                float e1 = __expf(acc[mt][nt][2 * h + 1] - mx);
                rs += e0 + e1;
                *(__half2*)&Pb[(size_t)r * NL + col] = __floats2half2_rn(e0, e1);
            }
            rs += __shfl_xor_sync(0xffffffffu, rs, 1);
            rs += __shfl_xor_sync(0xffffffffu, rs, 2);
            if (qid == 0) {
                atomicAdd(&g_sum[b * NL + r], __expf(mx) * rs);
                if (wn == 0)
                    g_rm[((size_t)(b * NJT + blockIdx.y) * NIT + blockIdx.x) * 128 + (r - j0)] = mx;
            }
        }
}

// ---------------------------------------------------------------------------
// Kernel 3 (fp16 mma, 5-stage pipeline, prep fused in-kernel):
// out[b][c][j] = x[b][c][j] + g * osc_j * sum_it w(j,it) sum_{i in it} P' X
// ---------------------------------------------------------------------------
#define ICH 32
#define NCHK (NL / ICH)             // 64
#define NSTG 5
#define ROWH 40
#define HTILE (128 * ROWH)
#define HSTG (2 * HTILE)
#define SMEM_OUT (NSTG * HSTG * 2)  // 102400 B

__global__ __launch_bounds__(256, 2) void k_out_h(const float* __restrict__ x,
                                                  const float* __restrict__ gam,
                                                  float* __restrict__ out) {
    extern __shared__ char smraw[];
    __shared__ float ws2[NIT][128];
    __shared__ float osc_s[128];
    const uint32_t sb = smem_u32(smraw);
    const int tid = threadIdx.x;
    const int b = blockIdx.z;
    const int c0 = blockIdx.y * 128;
    const int j0 = blockIdx.x * 128;
    const __half* xhb = g_Xh + (size_t)b * NC * NL;
    const __half* phb = g_P + (size_t)b * NL * NL;

    // in-kernel prep: per-row C_j, per-(row, i-tile) weights, output scale
    if (tid < 128) {
        const size_t base = (size_t)(b * NJT + blockIdx.x) * NIT * 128 + tid;
        float mv[NIT];
        float C = -1e30f;
#pragma unroll
        for (int it = 0; it < NIT; it++) {
            mv[it] = g_rm[base + it * 128];
            C = fmaxf(C, mv[it]);
        }
#pragma unroll
        for (int it = 0; it < NIT; it++)
            ws2[it][tid] = __expf(mv[it] - C);
        osc_s[tid] = __expf(C) / g_sum[b * NL + j0 + tid];
    }

    auto load_chunk = [&](int n) {
        if (n < NCHK) {
            const int stg = n % NSTG;
            const int i0 = n * ICH;
            const uint32_t xbase = sb + (uint32_t)(stg * HSTG) * 2;
            const uint32_t pbase = xbase + HTILE * 2;
#pragma unroll
            for (int u = 0; u < 2; u++) {
                int e = tid + u * 256;
                int r = e >> 2, seg = e & 3;
                cp16(xbase + (r * ROWH + seg * 8) * 2, xhb + (size_t)(c0 + r) * NL + i0 + seg * 8);
            }
#pragma unroll
            for (int u = 0; u < 2; u++) {
                int e = tid + u * 256;
                int r = e >> 2, seg = e & 3;
                cp16(pbase + (r * ROWH + seg * 8) * 2, phb + (size_t)(j0 + r) * NL + i0 + seg * 8);
            }
        }
        asm volatile("cp.async.commit_group;\n" ::: "memory");
    };

    const int wid = tid >> 5, lane = tid & 31;
    const int wm = wid & 3;
    const int wn = wid >> 2;
    const int grp = lane >> 2, qid = lane & 3;
    const int rowA = (lane & 7) + ((lane >> 3) & 1) * 8;
    const int colA = (lane >> 4) * 8;
    const int rowB = (lane & 7) + (lane >> 4) * 8;
    const int colB = ((lane >> 3) & 1) * 8;

    float acc[2][8][4];
#pragma unroll
    for (int mt = 0; mt < 2; mt++)
#pragma unroll
        for (int nt = 0; nt < 8; nt++)
#pragma unroll
            for (int q = 0; q < 4; q++) acc[mt][nt][q] = 0.f;

    __half2 wha[4], whb[4];

    auto compute_chunk = [&](int n) {
        const uint32_t xsb = sb + (uint32_t)((n % NSTG) * HSTG) * 2;
        const uint32_t psb = xsb + HTILE * 2;
#pragma unroll
        for (int kh16 = 0; kh16 < 2; kh16++) {
            const int k = kh16 * 16;
            uint32_t a[2][4];
#pragma unroll
            for (int mt = 0; mt < 2; mt++)
                ldm4(a[mt], xsb + ((wm * 32 + mt * 16 + rowA) * ROWH + k + colA) * 2);
#pragma unroll
            for (int p = 0; p < 4; p++) {
                uint32_t b4[4];
                ldm4(b4, psb + ((wn * 64 + p * 16 + rowB) * ROWH + k + colB) * 2);
                {
                    __half2 t0 = __hmul2(*(__half2*)&b4[0], wha[p]);
                    __half2 t1 = __hmul2(*(__half2*)&b4[1], wha[p]);
                    __half2 t2 = __hmul2(*(__half2*)&b4[2], whb[p]);
                    __half2 t3 = __hmul2(*(__half2*)&b4[3], whb[p]);
                    b4[0] = *(uint32_t*)&t0; b4[1] = *(uint32_t*)&t1;
                    b4[2] = *(uint32_t*)&t2; b4[3] = *(uint32_t*)&t3;
                }
                MMA_F16(acc[0][2 * p], a[0], b4[0], b4[1]);
                MMA_F16(acc[1][2 * p], a[1], b4[0], b4[1]);
                MMA_F16(acc[0][2 * p + 1], a[0], b4[2], b4[3]);
                MMA_F16(acc[1][2 * p + 1], a[1], b4[2], b4[3]);
            }
        }
    };

    load_chunk(0);
    load_chunk(1);
    load_chunk(2);

    for (int g = 0; g < NCHK / 2; g++) {
        asm volatile("cp.async.wait_group 1;\n" ::: "memory");
        __syncthreads();

        if ((g & 1) == 0) {      // new i-tile: refresh per-row weights
            const int it = g >> 1;
#pragma unroll
            for (int p = 0; p < 4; p++) {
                wha[p] = __float2half2_rn(ws2[it][wn * 64 + p * 16 + grp]);
                whb[p] = __float2half2_rn(ws2[it][wn * 64 + p * 16 + grp + 8]);
            }
        }

        load_chunk(2 * g + 3);
        compute_chunk(2 * g);
        load_chunk(2 * g + 4);
        compute_chunk(2 * g + 1);
    }

    const float g = *gam;
    const float* xb = x + (size_t)b * NC * NL;
    float* ob = out + (size_t)b * NC * NL;
    float2 rv[8];
#pragma unroll
    for (int nt = 0; nt < 8; nt++) {
        const int jl = wn * 64 + nt * 8 + qid * 2;
        rv[nt] = make_float2(osc_s[jl], osc_s[jl + 1]);
    }

#pragma unroll
    for (int mt = 0; mt < 2; mt++) {
        const int c = c0 + wm * 32 + mt * 16 + grp;
#pragma unroll
        for (int nt = 0; nt < 8; nt++) {
            const int j = j0 + wn * 64 + nt * 8 + qid * 2;
            {
                const size_t o = (size_t)c * NL + j;
                float2 xv = *(const float2*)(xb + o);
                float2 r = make_float2(xv.x + g * rv[nt].x * acc[mt][nt][0],
                                       xv.y + g * rv[nt].y * acc[mt][nt][1]);
                *(float2*)(ob + o) = r;
            }
            {
                const size_t o = (size_t)(c + 8) * NL + j;
                float2 xv = *(const float2*)(xb + o);
                float2 r = make_float2(xv.x + g * rv[nt].x * acc[mt][nt][2],
                                       xv.y + g * rv[nt].y * acc[mt][nt][3]);
                *(float2*)(ob + o) = r;
            }
        }
    }
}

// ---------------------------------------------------------------------------
extern "C" void kernel_launch(void* const* d_in, const int* in_sizes, int n_in,
                              void* d_out, int out_size) {
    (void)in_sizes; (void)n_in; (void)out_size;
    const float* x   = (const float*)d_in[0];
    const float* W1  = (const float*)d_in[1];
    const float* W2  = (const float*)d_in[2];
    const float* gam = (const float*)d_in[3];
    float* out = (float*)d_out;

    cudaFuncSetAttribute(k_proj_mma, cudaFuncAttributeMaxDynamicSharedMemorySize, SMEM_PROJ);
    cudaFuncSetAttribute(k_scores_mma, cudaFuncAttributeMaxDynamicSharedMemorySize, SMEM_SC);
    cudaFuncSetAttribute(k_out_h, cudaFuncAttributeMaxDynamicSharedMemorySize, SMEM_OUT);

    k_zero      <<<NB * NL / 1024, 1024>>>();
    k_proj_mma  <<<dim3(NL / 64, NB), 256, SMEM_PROJ>>>(x, W1, W2);
    k_scores_mma<<<dim3(NIT, NJT, NB), 256, SMEM_SC>>>();
    k_out_h     <<<dim3(NL / 128, NC / 128, NB), 256, SMEM_OUT>>>(x, gam, out);
}

// round 16
// speedup vs baseline: 1.2629x; 1.0487x over previous
#include <cuda_runtime.h>
#include <cuda_fp16.h>
#include <cstdint>

#define NB 8
#define NC 512
#define NL 2048
#define NT 64
#define NJT (NL / 128)   // 16 j-tiles
#define NIT (NL / 128)   // 16 i-tiles

// Scratch (static device globals — no allocation in kernel_launch)
__device__ __half g_Qh[NB * NL * NT];
__device__ __half g_Kh[NB * NL * NT];
__device__ __half g_Kl[NB * NL * NT];
__device__ __half g_P[(size_t)NB * NL * NL];     // P' = exp(s - m_row,tile) fp16  64 MB
__device__ __half g_Xh[(size_t)NB * NC * NL];    // x fp16 (written by k_proj)     16 MB
__device__ float  g_sum[NB * NL];                // exact row sums of e^s
__device__ float  g_rm[NB * NJT * NIT * 128];    // per-(row, i-tile) max

__device__ __forceinline__ uint32_t smem_u32(const void* p) {
    uint32_t r;
    asm("{ .reg .u64 t; cvta.to.shared.u64 t, %1; cvt.u32.u64 %0, t; }" : "=r"(r) : "l"(p));
    return r;
}
__device__ __forceinline__ void cp16(uint32_t dst, const void* src) {
    asm volatile("cp.async.cg.shared.global [%0], [%1], 16;\n" :: "r"(dst), "l"(src));
}
__device__ __forceinline__ void ldm4(uint32_t* r, uint32_t addr) {
    asm volatile("ldmatrix.sync.aligned.m8n8.x4.shared.b16 {%0,%1,%2,%3}, [%4];"
                 : "=r"(r[0]), "=r"(r[1]), "=r"(r[2]), "=r"(r[3]) : "r"(addr));
}
__device__ __forceinline__ void ldm4t(uint32_t* r, uint32_t addr) {
    asm volatile("ldmatrix.sync.aligned.m8n8.x4.trans.shared.b16 {%0,%1,%2,%3}, [%4];"
                 : "=r"(r[0]), "=r"(r[1]), "=r"(r[2]), "=r"(r[3]) : "r"(addr));
}

#define MMA_F16(ac, A, b0v, b1v)                                              \
    asm volatile("mma.sync.aligned.m16n8k16.row.col.f32.f16.f16.f32 "         \
                 "{%0,%1,%2,%3}, {%4,%5,%6,%7}, {%8,%9}, {%0,%1,%2,%3};"      \
                 : "+f"(ac[0]), "+f"(ac[1]), "+f"(ac[2]), "+f"(ac[3])         \
                 : "r"(A[0]), "r"(A[1]), "r"(A[2]), "r"(A[3]),                \
                   "r"(b0v), "r"(b1v));

// ---------------------------------------------------------------------------
// Kernel 1 (fp16 hi/lo 3-term MMA): Q/K projection + fused x->fp16 emit +
// fused g_sum zeroing. Q stored hi-only (scores uses 2-term qh*(kh+kl)).
// ---------------------------------------------------------------------------
#define PXROW 72
#define P_XH 0
#define P_XL (64 * PXROW)
#define P_WH (2 * 64 * PXROW)
#define P_WL (2 * 64 * PXROW + 128 * PXROW)
#define SMEM_PROJ ((2 * 64 * PXROW + 2 * 128 * PXROW) * 2)   // 55296 B

__global__ __launch_bounds__(256, 2) void k_proj_mma(const float* __restrict__ x,
                                                     const float* __restrict__ W1,
                                                     const float* __restrict__ W2) {
    extern __shared__ __half smh[];
    const uint32_t sb = smem_u32(smh);
    const int tid = threadIdx.x;
    const int b = blockIdx.y;
    const int l0 = blockIdx.x * 64;
    const float* xb = x + (size_t)b * NC * NL;

    if (tid < 64) g_sum[b * NL + l0 + tid] = 0.f;   // fused k_zero

    const int wid = tid >> 5, lane = tid & 31;
    const int wm = wid & 1;
    const int wn = wid >> 1;
    const int grp = lane >> 2, qid = lane & 3;
    const int rowT = (lane & 7) + ((lane >> 4) & 1) * 8;
    const int colT = ((lane >> 3) & 1) * 8;
    const int rowB = (lane & 7) + (lane >> 4) * 8;
    const int colB = ((lane >> 3) & 1) * 8;

    float acc[2][4][4];
#pragma unroll
    for (int mt = 0; mt < 2; mt++)
#pragma unroll
        for (int nt = 0; nt < 4; nt++)
#pragma unroll
            for (int q = 0; q < 4; q++) acc[mt][nt][q] = 0.f;

    for (int ch = 0; ch < NC / 64; ch++) {
        const int c0 = ch * 64;
#pragma unroll
        for (int u = 0; u < 4; u++) {
            int f = tid + u * 256;
            int c = f >> 4, lq = f & 15;
            float4 v = *(const float4*)(xb + (size_t)(c0 + c) * NL + l0 + lq * 4);
            float vv[4] = {v.x, v.y, v.z, v.w};
            __half hh[4], hl[4];
#pragma unroll
            for (int j = 0; j < 4; j++) {
                hh[j] = __float2half_rn(vv[j]);
                hl[j] = __float2half_rn(vv[j] - __half2float(hh[j]));
            }
            *(uint2*)&smh[P_XH + c * PXROW + lq * 4] = *(uint2*)hh;
            *(uint2*)&smh[P_XL + c * PXROW + lq * 4] = *(uint2*)hl;
            *(uint2*)&g_Xh[((size_t)b * NC + c0 + c) * NL + l0 + lq * 4] = *(uint2*)hh;
        }
#pragma unroll
        for (int u = 0; u < 8; u++) {
            int f = tid + u * 256;
            int t = f >> 4, cq = f & 15;
            const float* wsrc = (t < 64) ? (W1 + t * NC) : (W2 + (t - 64) * NC);
            float4 v = *(const float4*)(wsrc + c0 + cq * 4);
            float vv[4] = {v.x, v.y, v.z, v.w};
            __half hh[4], hl[4];
#pragma unroll
            for (int j = 0; j < 4; j++) {
                hh[j] = __float2half_rn(vv[j]);
                hl[j] = __float2half_rn(vv[j] - __half2float(hh[j]));
            }
            *(uint2*)&smh[P_WH + t * PXROW + cq * 4] = *(uint2*)hh;
            *(uint2*)&smh[P_WL + t * PXROW + cq * 4] = *(uint2*)hl;
        }
        __syncthreads();

#pragma unroll
        for (int k16 = 0; k16 < 4; k16++) {
            const int k = k16 * 16;
            uint32_t ah[2][4], al[2][4];
#pragma unroll
            for (int mt = 0; mt < 2; mt++) {
                const uint32_t ao = ((k + rowT) * PXROW + wm * 32 + mt * 16 + colT) * 2;
                ldm4t(ah[mt], sb + P_XH * 2 + ao);
                ldm4t(al[mt], sb + P_XL * 2 + ao);
            }
#pragma unroll
            for (int p = 0; p < 2; p++) {
                const uint32_t bo = ((wn * 32 + p * 16 + rowB) * PXROW + k + colB) * 2;
                uint32_t bh[4], bl[4];
                ldm4(bh, sb + P_WH * 2 + bo);
                ldm4(bl, sb + P_WL * 2 + bo);
#pragma unroll
                for (int e = 0; e < 2; e++) {
                    const int nt = p * 2 + e;
#pragma unroll
                    for (int mt = 0; mt < 2; mt++) {
                        MMA_F16(acc[mt][nt], ah[mt], bh[2 * e], bh[2 * e + 1]);
                        MMA_F16(acc[mt][nt], ah[mt], bl[2 * e], bl[2 * e + 1]);
                        MMA_F16(acc[mt][nt], al[mt], bh[2 * e], bh[2 * e + 1]);
                    }
                }
            }
        }
        __syncthreads();
    }

#pragma unroll
    for (int mt = 0; mt < 2; mt++) {
#pragma unroll
        for (int nt = 0; nt < 4; nt++) {
            const int t = wn * 32 + nt * 8 + qid * 2;
#pragma unroll
            for (int hrow = 0; hrow < 2; hrow++) {
                const int l = l0 + wm * 32 + mt * 16 + grp + hrow * 8;
                float v0 = acc[mt][nt][hrow * 2 + 0];
                float v1 = acc[mt][nt][hrow * 2 + 1];
                __half h0 = __float2half_rn(v0), h1 = __float2half_rn(v1);
                __half hp[2] = {h0, h1};
                const size_t off = ((size_t)b * NL + l) * NT + (t & 63);
                if (t < 64) {
                    *(uint32_t*)&g_Qh[off] = *(uint32_t*)hp;
                } else {
                    __half lp[2] = {__float2half_rn(v0 - __half2float(h0)),
                                    __float2half_rn(v1 - __half2float(h1))};
                    *(uint32_t*)&g_Kh[off] = *(uint32_t*)hp;
                    *(uint32_t*)&g_Kl[off] = *(uint32_t*)lp;
                }
            }
        }
    }
}

// ---------------------------------------------------------------------------
// Kernel 2 (fp16 2-term mma: qh*kh + qh*kl): P' = exp(s - m_row,tile) fp16,
// m_rt -> g_rm, exact row sums -> atomicAdd. Two-group staged tile load.
// ---------------------------------------------------------------------------
#define SROWH 72
#define STILE_H (128 * SROWH)
#define SMEM_SC (3 * STILE_H * 2)   // 55296 B  (Qh, Kh, Kl tiles)

__global__ __launch_bounds__(256) void k_scores_mma() {
    extern __shared__ char smraw[];
    const uint32_t sb = smem_u32(smraw);
    const int tid = threadIdx.x;
    const int b = blockIdx.z;
    const int j0 = blockIdx.y * 128;
    const int i0 = blockIdx.x * 128;

    const __half* srcs[3] = {g_Qh + ((size_t)b * NL + j0) * NT,
                             g_Kh + ((size_t)b * NL + i0) * NT,
                             g_Kl + ((size_t)b * NL + i0) * NT};
    // group A: k-cols 0..31 of all three tiles
#pragma unroll
    for (int t = 0; t < 3; t++) {
#pragma unroll
        for (int u = 0; u < 2; u++) {
            int e = tid + u * 256;
            int r = e >> 2, seg = e & 3;
            cp16(sb + (t * STILE_H + r * SROWH + seg * 8) * 2,
                 srcs[t] + (size_t)r * NT + seg * 8);
        }
    }
    asm volatile("cp.async.commit_group;\n" ::: "memory");
    // group B: k-cols 32..63
#pragma unroll
    for (int t = 0; t < 3; t++) {
#pragma unroll
        for (int u = 0; u < 2; u++) {
            int e = tid + u * 256;
            int r = e >> 2, seg = 4 + (e & 3);
            cp16(sb + (t * STILE_H + r * SROWH + seg * 8) * 2,
                 srcs[t] + (size_t)r * NT + seg * 8);
        }
    }
    asm volatile("cp.async.commit_group;\n" ::: "memory");

    const int wid = tid >> 5, lane = tid & 31;
    const int wm = wid & 3;
    const int wn = wid >> 2;
    const int grp = lane >> 2, qid = lane & 3;
    const int rowA = (lane & 7) + ((lane >> 3) & 1) * 8;
    const int colA = (lane >> 4) * 8;
    const int rowB = (lane & 7) + (lane >> 4) * 8;
    const int colB = ((lane >> 3) & 1) * 8;

    const uint32_t qh_b = sb;
    const uint32_t kh_b = sb + STILE_H * 2;
    const uint32_t kl_b = sb + 2 * STILE_H * 2;

    float acc[2][8][4];
#pragma unroll
    for (int mt = 0; mt < 2; mt++)
#pragma unroll
        for (int nt = 0; nt < 8; nt++)
#pragma unroll
            for (int q = 0; q < 4; q++) acc[mt][nt][q] = 0.f;

    auto compute_k16 = [&](int kh16) {
        const int k = kh16 * 16;
        uint32_t ah[2][4];
#pragma unroll
        for (int mt = 0; mt < 2; mt++) {
            const uint32_t ao = ((wm * 32 + mt * 16 + rowA) * SROWH + k + colA) * 2;
            ldm4(ah[mt], qh_b + ao);
        }
#pragma unroll
        for (int p = 0; p < 4; p++) {
            const uint32_t bo = ((wn * 64 + p * 16 + rowB) * SROWH + k + colB) * 2;
            uint32_t bh[4], bl[4];
            ldm4(bh, kh_b + bo);
            ldm4(bl, kl_b + bo);
#pragma unroll
            for (int e = 0; e < 2; e++) {
                const int nt = p * 2 + e;
#pragma unroll
                for (int mt = 0; mt < 2; mt++) {
                    MMA_F16(acc[mt][nt], ah[mt], bh[2 * e], bh[2 * e + 1]);
                    MMA_F16(acc[mt][nt], ah[mt], bl[2 * e], bl[2 * e + 1]);
                }
            }
        }
    };

    asm volatile("cp.async.wait_group 1;\n" ::: "memory");
    __syncthreads();
    compute_k16(0);
    compute_k16(1);
    asm volatile("cp.async.wait_group 0;\n" ::: "memory");
    __syncthreads();
    compute_k16(2);
    compute_k16(3);

    // per-row (within tile) max: quad reduce, then combine the 2 wn warps
    float lmax[2][2];
#pragma unroll
    for (int mt = 0; mt < 2; mt++)
#pragma unroll
        for (int h = 0; h < 2; h++) {
            float m = -1e30f;
#pragma unroll
            for (int nt = 0; nt < 8; nt++)
                m = fmaxf(m, fmaxf(acc[mt][nt][2 * h], acc[mt][nt][2 * h + 1]));
            m = fmaxf(m, __shfl_xor_sync(0xffffffffu, m, 1));
            m = fmaxf(m, __shfl_xor_sync(0xffffffffu, m, 2));
            lmax[mt][h] = m;
        }
    float* red = (float*)smraw;
    __syncthreads();
    if (qid == 0) {
#pragma unroll
        for (int mt = 0; mt < 2; mt++)
#pragma unroll
            for (int h = 0; h < 2; h++)
                red[(((wn * 4 + wm) * 2 + mt) * 2 + h) * 8 + grp] = lmax[mt][h];
    }
    __syncthreads();

    __half* Pb = g_P + (size_t)b * NL * NL;
#pragma unroll
    for (int mt = 0; mt < 2; mt++)
#pragma unroll
        for (int h = 0; h < 2; h++) {
            const float mx = fmaxf(lmax[mt][h],
                red[((((1 - wn) * 4 + wm) * 2 + mt) * 2 + h) * 8 + grp]);
            const int r = j0 + wm * 32 + mt * 16 + grp + h * 8;
            float rs = 0.f;
#pragma unroll
            for (int nt = 0; nt < 8; nt++) {
                const int col = i0 + wn * 64 + nt * 8 + qid * 2;
                float e0 = __expf(acc[mt][nt][2 * h] - mx);
                float e1 = __expf(acc[mt][nt][2 * h + 1] - mx);
                rs += e0 + e1;
                *(__half2*)&Pb[(size_t)r * NL + col] = __floats2half2_rn(e0, e1);
            }
            rs += __shfl_xor_sync(0xffffffffu, rs, 1);
            rs += __shfl_xor_sync(0xffffffffu, rs, 2);
            if (qid == 0) {
                atomicAdd(&g_sum[b * NL + r], __expf(mx) * rs);
                if (wn == 0)
                    g_rm[((size_t)(b * NJT + blockIdx.y) * NIT + blockIdx.x) * 128 + (r - j0)] = mx;
            }
        }
}

// ---------------------------------------------------------------------------
// Kernel 3 (fp16 mma, 5-stage pipeline, prep fused in-kernel):
// out[b][c][j] = x[b][c][j] + g * osc_j * sum_it w(j,it) sum_{i in it} P' X
// ---------------------------------------------------------------------------
#define ICH 32
#define NCHK (NL / ICH)             // 64
#define NSTG 5
#define ROWH 40
#define HTILE (128 * ROWH)
#define HSTG (2 * HTILE)
#define SMEM_OUT (NSTG * HSTG * 2)  // 102400 B

__global__ __launch_bounds__(256, 2) void k_out_h(const float* __restrict__ x,
                                                  const float* __restrict__ gam,
                                                  float* __restrict__ out) {
    extern __shared__ char smraw[];
    __shared__ float ws2[NIT][128];
    __shared__ float osc_s[128];
    const uint32_t sb = smem_u32(smraw);
    const int tid = threadIdx.x;
    const int b = blockIdx.z;
    const int c0 = blockIdx.y * 128;
    const int j0 = blockIdx.x * 128;
    const __half* xhb = g_Xh + (size_t)b * NC * NL;
    const __half* phb = g_P + (size_t)b * NL * NL;

    // in-kernel prep: per-row C_j, per-(row, i-tile) weights, output scale
    if (tid < 128) {
        const size_t base = (size_t)(b * NJT + blockIdx.x) * NIT * 128 + tid;
        float mv[NIT];
        float C = -1e30f;
#pragma unroll
        for (int it = 0; it < NIT; it++) {
            mv[it] = g_rm[base + it * 128];
            C = fmaxf(C, mv[it]);
        }
#pragma unroll
        for (int it = 0; it < NIT; it++)
            ws2[it][tid] = __expf(mv[it] - C);
        osc_s[tid] = __expf(C) / g_sum[b * NL + j0 + tid];
    }

    auto load_chunk = [&](int n) {
        if (n < NCHK) {
            const int stg = n % NSTG;
            const int i0 = n * ICH;
            const uint32_t xbase = sb + (uint32_t)(stg * HSTG) * 2;
            const uint32_t pbase = xbase + HTILE * 2;
#pragma unroll
            for (int u = 0; u < 2; u++) {
                int e = tid + u * 256;
                int r = e >> 2, seg = e & 3;
                cp16(xbase + (r * ROWH + seg * 8) * 2, xhb + (size_t)(c0 + r) * NL + i0 + seg * 8);
            }
#pragma unroll
            for (int u = 0; u < 2; u++) {
                int e = tid + u * 256;
                int r = e >> 2, seg = e & 3;
                cp16(pbase + (r * ROWH + seg * 8) * 2, phb + (size_t)(j0 + r) * NL + i0 + seg * 8);
            }
        }
        asm volatile("cp.async.commit_group;\n" ::: "memory");
    };

    const int wid = tid >> 5, lane = tid & 31;
    const int wm = wid & 3;
    const int wn = wid >> 2;
    const int grp = lane >> 2, qid = lane & 3;
    const int rowA = (lane & 7) + ((lane >> 3) & 1) * 8;
    const int colA = (lane >> 4) * 8;
    const int rowB = (lane & 7) + (lane >> 4) * 8;
    const int colB = ((lane >> 3) & 1) * 8;

    float acc[2][8][4];
#pragma unroll
    for (int mt = 0; mt < 2; mt++)
#pragma unroll
        for (int nt = 0; nt < 8; nt++)
#pragma unroll
            for (int q = 0; q < 4; q++) acc[mt][nt][q] = 0.f;

    __half2 wha[4], whb[4];

    auto compute_chunk = [&](int n) {
        const uint32_t xsb = sb + (uint32_t)((n % NSTG) * HSTG) * 2;
        const uint32_t psb = xsb + HTILE * 2;
#pragma unroll
        for (int kh16 = 0; kh16 < 2; kh16++) {
            const int k = kh16 * 16;
            uint32_t a[2][4];
#pragma unroll
            for (int mt = 0; mt < 2; mt++)
                ldm4(a[mt], xsb + ((wm * 32 + mt * 16 + rowA) * ROWH + k + colA) * 2);
#pragma unroll
            for (int p = 0; p < 4; p++) {
                uint32_t b4[4];
                ldm4(b4, psb + ((wn * 64 + p * 16 + rowB) * ROWH + k + colB) * 2);
                {
                    __half2 t0 = __hmul2(*(__half2*)&b4[0], wha[p]);
                    __half2 t1 = __hmul2(*(__half2*)&b4[1], wha[p]);
                    __half2 t2 = __hmul2(*(__half2*)&b4[2], whb[p]);
                    __half2 t3 = __hmul2(*(__half2*)&b4[3], whb[p]);
                    b4[0] = *(uint32_t*)&t0; b4[1] = *(uint32_t*)&t1;
                    b4[2] = *(uint32_t*)&t2; b4[3] = *(uint32_t*)&t3;
                }
                MMA_F16(acc[0][2 * p], a[0], b4[0], b4[1]);
                MMA_F16(acc[1][2 * p], a[1], b4[0], b4[1]);
                MMA_F16(acc[0][2 * p + 1], a[0], b4[2], b4[3]);
                MMA_F16(acc[1][2 * p + 1], a[1], b4[2], b4[3]);
            }
        }
    };

    load_chunk(0);
    load_chunk(1);
    load_chunk(2);

    for (int g = 0; g < NCHK / 2; g++) {
        asm volatile("cp.async.wait_group 1;\n" ::: "memory");
        __syncthreads();

        if ((g & 1) == 0) {      // new i-tile: refresh per-row weights
            const int it = g >> 1;
#pragma unroll
            for (int p = 0; p < 4; p++) {
                wha[p] = __float2half2_rn(ws2[it][wn * 64 + p * 16 + grp]);
                whb[p] = __float2half2_rn(ws2[it][wn * 64 + p * 16 + grp + 8]);
            }
        }

        load_chunk(2 * g + 3);
        compute_chunk(2 * g);
        load_chunk(2 * g + 4);
        compute_chunk(2 * g + 1);
    }

    const float g = *gam;
    const float* xb = x + (size_t)b * NC * NL;
    float* ob = out + (size_t)b * NC * NL;
    float2 rv[8];
#pragma unroll
    for (int nt = 0; nt < 8; nt++) {
        const int jl = wn * 64 + nt * 8 + qid * 2;
        rv[nt] = make_float2(osc_s[jl], osc_s[jl + 1]);
    }

#pragma unroll
    for (int mt = 0; mt < 2; mt++) {
        const int c = c0 + wm * 32 + mt * 16 + grp;
#pragma unroll
        for (int nt = 0; nt < 8; nt++) {
            const int j = j0 + wn * 64 + nt * 8 + qid * 2;
            {
                const size_t o = (size_t)c * NL + j;
                float2 xv = *(const float2*)(xb + o);
                float2 r = make_float2(xv.x + g * rv[nt].x * acc[mt][nt][0],
                                       xv.y + g * rv[nt].y * acc[mt][nt][1]);
                *(float2*)(ob + o) = r;
            }
            {
                const size_t o = (size_t)(c + 8) * NL + j;
                float2 xv = *(const float2*)(xb + o);
                float2 r = make_float2(xv.x + g * rv[nt].x * acc[mt][nt][2],
                                       xv.y + g * rv[nt].y * acc[mt][nt][3]);
                *(float2*)(ob + o) = r;
            }
        }
    }
}

// ---------------------------------------------------------------------------
extern "C" void kernel_launch(void* const* d_in, const int* in_sizes, int n_in,
                              void* d_out, int out_size) {
    (void)in_sizes; (void)n_in; (void)out_size;
    const float* x   = (const float*)d_in[0];
    const float* W1  = (const float*)d_in[1];
    const float* W2  = (const float*)d_in[2];
    const float* gam = (const float*)d_in[3];
    float* out = (float*)d_out;

    cudaFuncSetAttribute(k_proj_mma, cudaFuncAttributeMaxDynamicSharedMemorySize, SMEM_PROJ);
    cudaFuncSetAttribute(k_scores_mma, cudaFuncAttributeMaxDynamicSharedMemorySize, SMEM_SC);
    cudaFuncSetAttribute(k_out_h, cudaFuncAttributeMaxDynamicSharedMemorySize, SMEM_OUT);

    k_proj_mma  <<<dim3(NL / 64, NB), 256, SMEM_PROJ>>>(x, W1, W2);
    k_scores_mma<<<dim3(NIT, NJT, NB), 256, SMEM_SC>>>();
    k_out_h     <<<dim3(NL / 128, NC / 128, NB), 256, SMEM_OUT>>>(x, gam, out);
}

// round 17
// speedup vs baseline: 1.3010x; 1.0301x over previous
#include <cuda_runtime.h>
#include <cuda_fp16.h>
#include <cstdint>

#define NB 8
#define NC 512
#define NL 2048
#define NT 64
#define NJT (NL / 128)   // 16 j-tiles
#define NIT (NL / 128)   // 16 i-tiles

// Scratch (static device globals — no allocation in kernel_launch)
__device__ __half g_Qh[NB * NL * NT];
__device__ __half g_Kh[NB * NL * NT];
__device__ __half g_P[(size_t)NB * NL * NL];     // P' = exp(s - m_row,tile) fp16  64 MB
__device__ __half g_Xh[(size_t)NB * NC * NL];    // x fp16 (written by k_proj)     16 MB
__device__ float  g_sum[NB * NL];                // exact row sums of e^s
__device__ float  g_rm[NB * NJT * NIT * 128];    // per-(row, i-tile) max

__device__ __forceinline__ uint32_t smem_u32(const void* p) {
    uint32_t r;
    asm("{ .reg .u64 t; cvta.to.shared.u64 t, %1; cvt.u32.u64 %0, t; }" : "=r"(r) : "l"(p));
    return r;
}
__device__ __forceinline__ void cp16(uint32_t dst, const void* src) {
    asm volatile("cp.async.cg.shared.global [%0], [%1], 16;\n" :: "r"(dst), "l"(src));
}
__device__ __forceinline__ void ldm4(uint32_t* r, uint32_t addr) {
    asm volatile("ldmatrix.sync.aligned.m8n8.x4.shared.b16 {%0,%1,%2,%3}, [%4];"
                 : "=r"(r[0]), "=r"(r[1]), "=r"(r[2]), "=r"(r[3]) : "r"(addr));
}
__device__ __forceinline__ void ldm4t(uint32_t* r, uint32_t addr) {
    asm volatile("ldmatrix.sync.aligned.m8n8.x4.trans.shared.b16 {%0,%1,%2,%3}, [%4];"
                 : "=r"(r[0]), "=r"(r[1]), "=r"(r[2]), "=r"(r[3]) : "r"(addr));
}

#define MMA_F16(ac, A, b0v, b1v)                                              \
    asm volatile("mma.sync.aligned.m16n8k16.row.col.f32.f16.f16.f32 "         \
                 "{%0,%1,%2,%3}, {%4,%5,%6,%7}, {%8,%9}, {%0,%1,%2,%3};"      \
                 : "+f"(ac[0]), "+f"(ac[1]), "+f"(ac[2]), "+f"(ac[3])         \
                 : "r"(A[0]), "r"(A[1]), "r"(A[2]), "r"(A[3]),                \
                   "r"(b0v), "r"(b1v));

// ---------------------------------------------------------------------------
// Kernel 1 (fp16 hi/lo 3-term MMA): Q/K projection + fused x->fp16 emit +
// fused g_sum zeroing. Q and K stored hi-only (scores uses qh*kh).
// Projection itself keeps fp32-equivalent precision via the 3-term split.
// ---------------------------------------------------------------------------
#define PXROW 72
#define P_XH 0
#define P_XL (64 * PXROW)
#define P_WH (2 * 64 * PXROW)
#define P_WL (2 * 64 * PXROW + 128 * PXROW)
#define SMEM_PROJ ((2 * 64 * PXROW + 2 * 128 * PXROW) * 2)   // 55296 B

__global__ __launch_bounds__(256, 2) void k_proj_mma(const float* __restrict__ x,
                                                     const float* __restrict__ W1,
                                                     const float* __restrict__ W2) {
    extern __shared__ __half smh[];
    const uint32_t sb = smem_u32(smh);
    const int tid = threadIdx.x;
    const int b = blockIdx.y;
    const int l0 = blockIdx.x * 64;
    const float* xb = x + (size_t)b * NC * NL;

    if (tid < 64) g_sum[b * NL + l0 + tid] = 0.f;   // fused k_zero

    const int wid = tid >> 5, lane = tid & 31;
    const int wm = wid & 1;
    const int wn = wid >> 1;
    const int grp = lane >> 2, qid = lane & 3;
    const int rowT = (lane & 7) + ((lane >> 4) & 1) * 8;
    const int colT = ((lane >> 3) & 1) * 8;
    const int rowB = (lane & 7) + (lane >> 4) * 8;
    const int colB = ((lane >> 3) & 1) * 8;

    float acc[2][4][4];
#pragma unroll
    for (int mt = 0; mt < 2; mt++)
#pragma unroll
        for (int nt = 0; nt < 4; nt++)
#pragma unroll
            for (int q = 0; q < 4; q++) acc[mt][nt][q] = 0.f;

    for (int ch = 0; ch < NC / 64; ch++) {
        const int c0 = ch * 64;
#pragma unroll
        for (int u = 0; u < 4; u++) {
            int f = tid + u * 256;
            int c = f >> 4, lq = f & 15;
            float4 v = *(const float4*)(xb + (size_t)(c0 + c) * NL + l0 + lq * 4);
            float vv[4] = {v.x, v.y, v.z, v.w};
            __half hh[4], hl[4];
#pragma unroll
            for (int j = 0; j < 4; j++) {
                hh[j] = __float2half_rn(vv[j]);
                hl[j] = __float2half_rn(vv[j] - __half2float(hh[j]));
            }
            *(uint2*)&smh[P_XH + c * PXROW + lq * 4] = *(uint2*)hh;
            *(uint2*)&smh[P_XL + c * PXROW + lq * 4] = *(uint2*)hl;
            *(uint2*)&g_Xh[((size_t)b * NC + c0 + c) * NL + l0 + lq * 4] = *(uint2*)hh;
        }
#pragma unroll
        for (int u = 0; u < 8; u++) {
            int f = tid + u * 256;
            int t = f >> 4, cq = f & 15;
            const float* wsrc = (t < 64) ? (W1 + t * NC) : (W2 + (t - 64) * NC);
            float4 v = *(const float4*)(wsrc + c0 + cq * 4);
            float vv[4] = {v.x, v.y, v.z, v.w};
            __half hh[4], hl[4];
#pragma unroll
            for (int j = 0; j < 4; j++) {
                hh[j] = __float2half_rn(vv[j]);
                hl[j] = __float2half_rn(vv[j] - __half2float(hh[j]));
            }
            *(uint2*)&smh[P_WH + t * PXROW + cq * 4] = *(uint2*)hh;
            *(uint2*)&smh[P_WL + t * PXROW + cq * 4] = *(uint2*)hl;
        }
        __syncthreads();

#pragma unroll
        for (int k16 = 0; k16 < 4; k16++) {
            const int k = k16 * 16;
            uint32_t ah[2][4], al[2][4];
#pragma unroll
            for (int mt = 0; mt < 2; mt++) {
                const uint32_t ao = ((k + rowT) * PXROW + wm * 32 + mt * 16 + colT) * 2;
                ldm4t(ah[mt], sb + P_XH * 2 + ao);
                ldm4t(al[mt], sb + P_XL * 2 + ao);
            }
#pragma unroll
            for (int p = 0; p < 2; p++) {
                const uint32_t bo = ((wn * 32 + p * 16 + rowB) * PXROW + k + colB) * 2;
                uint32_t bh[4], bl[4];
                ldm4(bh, sb + P_WH * 2 + bo);
                ldm4(bl, sb + P_WL * 2 + bo);
#pragma unroll
                for (int e = 0; e < 2; e++) {
                    const int nt = p * 2 + e;
#pragma unroll
                    for (int mt = 0; mt < 2; mt++) {
                        MMA_F16(acc[mt][nt], ah[mt], bh[2 * e], bh[2 * e + 1]);
                        MMA_F16(acc[mt][nt], ah[mt], bl[2 * e], bl[2 * e + 1]);
                        MMA_F16(acc[mt][nt], al[mt], bh[2 * e], bh[2 * e + 1]);
                    }
                }
            }
        }
        __syncthreads();
    }

#pragma unroll
    for (int mt = 0; mt < 2; mt++) {
#pragma unroll
        for (int nt = 0; nt < 4; nt++) {
            const int t = wn * 32 + nt * 8 + qid * 2;
#pragma unroll
            for (int hrow = 0; hrow < 2; hrow++) {
                const int l = l0 + wm * 32 + mt * 16 + grp + hrow * 8;
                __half hp[2] = {__float2half_rn(acc[mt][nt][hrow * 2 + 0]),
                                __float2half_rn(acc[mt][nt][hrow * 2 + 1])};
                const size_t off = ((size_t)b * NL + l) * NT + (t & 63);
                if (t < 64) *(uint32_t*)&g_Qh[off] = *(uint32_t*)hp;
                else        *(uint32_t*)&g_Kh[off] = *(uint32_t*)hp;
            }
        }
    }
}

// ---------------------------------------------------------------------------
// Kernel 2 (fp16 single-term mma: qh*kh): P' = exp(s - m_row,tile) fp16,
// m_rt -> g_rm, exact row sums -> atomicAdd. Two-group staged tile load.
// ---------------------------------------------------------------------------
#define SROWH 72
#define STILE_H (128 * SROWH)
#define SMEM_SC (2 * STILE_H * 2)   // 36864 B  (Qh, Kh tiles)

__global__ __launch_bounds__(256) void k_scores_mma() {
    extern __shared__ char smraw[];
    const uint32_t sb = smem_u32(smraw);
    const int tid = threadIdx.x;
    const int b = blockIdx.z;
    const int j0 = blockIdx.y * 128;
    const int i0 = blockIdx.x * 128;

    const __half* srcs[2] = {g_Qh + ((size_t)b * NL + j0) * NT,
                             g_Kh + ((size_t)b * NL + i0) * NT};
    // group A: k-cols 0..31 of both tiles
#pragma unroll
    for (int t = 0; t < 2; t++) {
#pragma unroll
        for (int u = 0; u < 2; u++) {
            int e = tid + u * 256;
            int r = e >> 2, seg = e & 3;
            cp16(sb + (t * STILE_H + r * SROWH + seg * 8) * 2,
                 srcs[t] + (size_t)r * NT + seg * 8);
        }
    }
    asm volatile("cp.async.commit_group;\n" ::: "memory");
    // group B: k-cols 32..63
#pragma unroll
    for (int t = 0; t < 2; t++) {
#pragma unroll
        for (int u = 0; u < 2; u++) {
            int e = tid + u * 256;
            int r = e >> 2, seg = 4 + (e & 3);
            cp16(sb + (t * STILE_H + r * SROWH + seg * 8) * 2,
                 srcs[t] + (size_t)r * NT + seg * 8);
        }
    }
    asm volatile("cp.async.commit_group;\n" ::: "memory");

    const int wid = tid >> 5, lane = tid & 31;
    const int wm = wid & 3;
    const int wn = wid >> 2;
    const int grp = lane >> 2, qid = lane & 3;
    const int rowA = (lane & 7) + ((lane >> 3) & 1) * 8;
    const int colA = (lane >> 4) * 8;
    const int rowB = (lane & 7) + (lane >> 4) * 8;
    const int colB = ((lane >> 3) & 1) * 8;

    const uint32_t qh_b = sb;
    const uint32_t kh_b = sb + STILE_H * 2;

    float acc[2][8][4];
#pragma unroll
    for (int mt = 0; mt < 2; mt++)
#pragma unroll
        for (int nt = 0; nt < 8; nt++)
#pragma unroll
            for (int q = 0; q < 4; q++) acc[mt][nt][q] = 0.f;

    auto compute_k16 = [&](int kh16) {
        const int k = kh16 * 16;
        uint32_t ah[2][4];
#pragma unroll
        for (int mt = 0; mt < 2; mt++) {
            const uint32_t ao = ((wm * 32 + mt * 16 + rowA) * SROWH + k + colA) * 2;
            ldm4(ah[mt], qh_b + ao);
        }
#pragma unroll
        for (int p = 0; p < 4; p++) {
            const uint32_t bo = ((wn * 64 + p * 16 + rowB) * SROWH + k + colB) * 2;
            uint32_t bh[4];
            ldm4(bh, kh_b + bo);
#pragma unroll
            for (int e = 0; e < 2; e++) {
                const int nt = p * 2 + e;
#pragma unroll
                for (int mt = 0; mt < 2; mt++)
                    MMA_F16(acc[mt][nt], ah[mt], bh[2 * e], bh[2 * e + 1]);
            }
        }
    };

    asm volatile("cp.async.wait_group 1;\n" ::: "memory");
    __syncthreads();
    compute_k16(0);
    compute_k16(1);
    asm volatile("cp.async.wait_group 0;\n" ::: "memory");
    __syncthreads();
    compute_k16(2);
    compute_k16(3);

    // per-row (within tile) max: quad reduce, then combine the 2 wn warps
    float lmax[2][2];
#pragma unroll
    for (int mt = 0; mt < 2; mt++)
#pragma unroll
        for (int h = 0; h < 2; h++) {
            float m = -1e30f;
#pragma unroll
            for (int nt = 0; nt < 8; nt++)
                m = fmaxf(m, fmaxf(acc[mt][nt][2 * h], acc[mt][nt][2 * h + 1]));
            m = fmaxf(m, __shfl_xor_sync(0xffffffffu, m, 1));
            m = fmaxf(m, __shfl_xor_sync(0xffffffffu, m, 2));
            lmax[mt][h] = m;
        }
    float* red = (float*)smraw;
    __syncthreads();
    if (qid == 0) {
#pragma unroll
        for (int mt = 0; mt < 2; mt++)
#pragma unroll
            for (int h = 0; h < 2; h++)
                red[(((wn * 4 + wm) * 2 + mt) * 2 + h) * 8 + grp] = lmax[mt][h];
    }
    __syncthreads();

    __half* Pb = g_P + (size_t)b * NL * NL;
#pragma unroll
    for (int mt = 0; mt < 2; mt++)
#pragma unroll
        for (int h = 0; h < 2; h++) {
            const float mx = fmaxf(lmax[mt][h],
                red[((((1 - wn) * 4 + wm) * 2 + mt) * 2 + h) * 8 + grp]);
            const int r = j0 + wm * 32 + mt * 16 + grp + h * 8;
            float rs = 0.f;
#pragma unroll
            for (int nt = 0; nt < 8; nt++) {
                const int col = i0 + wn * 64 + nt * 8 + qid * 2;
                float e0 = __expf(acc[mt][nt][2 * h] - mx);
                float e1 = __expf(acc[mt][nt][2 * h + 1] - mx);
                rs += e0 + e1;
                *(__half2*)&Pb[(size_t)r * NL + col] = __floats2half2_rn(e0, e1);
            }
            rs += __shfl_xor_sync(0xffffffffu, rs, 1);
            rs += __shfl_xor_sync(0xffffffffu, rs, 2);
            if (qid == 0) {
                atomicAdd(&g_sum[b * NL + r], __expf(mx) * rs);
                if (wn == 0)
                    g_rm[((size_t)(b * NJT + blockIdx.y) * NIT + blockIdx.x) * 128 + (r - j0)] = mx;
            }
        }
}

// ---------------------------------------------------------------------------
// Kernel 3 (fp16 mma, 5-stage pipeline, prep fused in-kernel):
// out[b][c][j] = x[b][c][j] + g * osc_j * sum_it w(j,it) sum_{i in it} P' X
// ---------------------------------------------------------------------------
#define ICH 32
#define NCHK (NL / ICH)             // 64
#define NSTG 5
#define ROWH 40
#define HTILE (128 * ROWH)
#define HSTG (2 * HTILE)
#define SMEM_OUT (NSTG * HSTG * 2)  // 102400 B

__global__ __launch_bounds__(256, 2) void k_out_h(const float* __restrict__ x,
                                                  const float* __restrict__ gam,
                                                  float* __restrict__ out) {
    extern __shared__ char smraw[];
    __shared__ float ws2[NIT][128];
    __shared__ float osc_s[128];
    const uint32_t sb = smem_u32(smraw);
    const int tid = threadIdx.x;
    const int b = blockIdx.z;
    const int c0 = blockIdx.y * 128;
    const int j0 = blockIdx.x * 128;
    const __half* xhb = g_Xh + (size_t)b * NC * NL;
    const __half* phb = g_P + (size_t)b * NL * NL;

    // in-kernel prep: per-row C_j, per-(row, i-tile) weights, output scale
    if (tid < 128) {
        const size_t base = (size_t)(b * NJT + blockIdx.x) * NIT * 128 + tid;
        float mv[NIT];
        float C = -1e30f;
#pragma unroll
        for (int it = 0; it < NIT; it++) {
            mv[it] = g_rm[base + it * 128];
            C = fmaxf(C, mv[it]);
        }
#pragma unroll
        for (int it = 0; it < NIT; it++)
            ws2[it][tid] = __expf(mv[it] - C);
        osc_s[tid] = __expf(C) / g_sum[b * NL + j0 + tid];
    }

    auto load_chunk = [&](int n) {
        if (n < NCHK) {
            const int stg = n % NSTG;
            const int i0 = n * ICH;
            const uint32_t xbase = sb + (uint32_t)(stg * HSTG) * 2;
            const uint32_t pbase = xbase + HTILE * 2;
#pragma unroll
            for (int u = 0; u < 2; u++) {
                int e = tid + u * 256;
                int r = e >> 2, seg = e & 3;
                cp16(xbase + (r * ROWH + seg * 8) * 2, xhb + (size_t)(c0 + r) * NL + i0 + seg * 8);
            }
#pragma unroll
            for (int u = 0; u < 2; u++) {
                int e = tid + u * 256;
                int r = e >> 2, seg = e & 3;
                cp16(pbase + (r * ROWH + seg * 8) * 2, phb + (size_t)(j0 + r) * NL + i0 + seg * 8);
            }
        }
        asm volatile("cp.async.commit_group;\n" ::: "memory");
    };

    const int wid = tid >> 5, lane = tid & 31;
    const int wm = wid & 3;
    const int wn = wid >> 2;
    const int grp = lane >> 2, qid = lane & 3;
    const int rowA = (lane & 7) + ((lane >> 3) & 1) * 8;
    const int colA = (lane >> 4) * 8;
    const int rowB = (lane & 7) + (lane >> 4) * 8;
    const int colB = ((lane >> 3) & 1) * 8;

    float acc[2][8][4];
#pragma unroll
    for (int mt = 0; mt < 2; mt++)
#pragma unroll
        for (int nt = 0; nt < 8; nt++)
#pragma unroll
            for (int q = 0; q < 4; q++) acc[mt][nt][q] = 0.f;

    __half2 wha[4], whb[4];

    auto compute_chunk = [&](int n) {
        const uint32_t xsb = sb + (uint32_t)((n % NSTG) * HSTG) * 2;
        const uint32_t psb = xsb + HTILE * 2;
#pragma unroll
        for (int kh16 = 0; kh16 < 2; kh16++) {
            const int k = kh16 * 16;
            uint32_t a[2][4];
#pragma unroll
            for (int mt = 0; mt < 2; mt++)
                ldm4(a[mt], xsb + ((wm * 32 + mt * 16 + rowA) * ROWH + k + colA) * 2);
#pragma unroll
            for (int p = 0; p < 4; p++) {
                uint32_t b4[4];
                ldm4(b4, psb + ((wn * 64 + p * 16 + rowB) * ROWH + k + colB) * 2);
                {
                    __half2 t0 = __hmul2(*(__half2*)&b4[0], wha[p]);
                    __half2 t1 = __hmul2(*(__half2*)&b4[1], wha[p]);
                    __half2 t2 = __hmul2(*(__half2*)&b4[2], whb[p]);
                    __half2 t3 = __hmul2(*(__half2*)&b4[3], whb[p]);
                    b4[0] = *(uint32_t*)&t0; b4[1] = *(uint32_t*)&t1;
                    b4[2] = *(uint32_t*)&t2; b4[3] = *(uint32_t*)&t3;
                }
                MMA_F16(acc[0][2 * p], a[0], b4[0], b4[1]);
                MMA_F16(acc[1][2 * p], a[1], b4[0], b4[1]);
                MMA_F16(acc[0][2 * p + 1], a[0], b4[2], b4[3]);
                MMA_F16(acc[1][2 * p + 1], a[1], b4[2], b4[3]);
            }
        }
    };

    load_chunk(0);
    load_chunk(1);
    load_chunk(2);

    for (int g = 0; g < NCHK / 2; g++) {
        asm volatile("cp.async.wait_group 1;\n" ::: "memory");
        __syncthreads();

        if ((g & 1) == 0) {      // new i-tile: refresh per-row weights
            const int it = g >> 1;
#pragma unroll
            for (int p = 0; p < 4; p++) {
                wha[p] = __float2half2_rn(ws2[it][wn * 64 + p * 16 + grp]);
                whb[p] = __float2half2_rn(ws2[it][wn * 64 + p * 16 + grp + 8]);
            }
        }

        load_chunk(2 * g + 3);
        compute_chunk(2 * g);
        load_chunk(2 * g + 4);
        compute_chunk(2 * g + 1);
    }

    const float g = *gam;
    const float* xb = x + (size_t)b * NC * NL;
    float* ob = out + (size_t)b * NC * NL;
    float2 rv[8];
#pragma unroll
    for (int nt = 0; nt < 8; nt++) {
        const int jl = wn * 64 + nt * 8 + qid * 2;
        rv[nt] = make_float2(osc_s[jl], osc_s[jl + 1]);
    }

#pragma unroll
    for (int mt = 0; mt < 2; mt++) {
        const int c = c0 + wm * 32 + mt * 16 + grp;
#pragma unroll
        for (int nt = 0; nt < 8; nt++) {
            const int j = j0 + wn * 64 + nt * 8 + qid * 2;
            {
                const size_t o = (size_t)c * NL + j;
                float2 xv = *(const float2*)(xb + o);
                float2 r = make_float2(xv.x + g * rv[nt].x * acc[mt][nt][0],
                                       xv.y + g * rv[nt].y * acc[mt][nt][1]);
                *(float2*)(ob + o) = r;
            }
            {
                const size_t o = (size_t)(c + 8) * NL + j;
                float2 xv = *(const float2*)(xb + o);
                float2 r = make_float2(xv.x + g * rv[nt].x * acc[mt][nt][2],
                                       xv.y + g * rv[nt].y * acc[mt][nt][3]);
                *(float2*)(ob + o) = r;
            }
        }
    }
}

// ---------------------------------------------------------------------------
extern "C" void kernel_launch(void* const* d_in, const int* in_sizes, int n_in,
                              void* d_out, int out_size) {
    (void)in_sizes; (void)n_in; (void)out_size;
    const float* x   = (const float*)d_in[0];
    const float* W1  = (const float*)d_in[1];
    const float* W2  = (const float*)d_in[2];
    const float* gam = (const float*)d_in[3];
    float* out = (float*)d_out;

    cudaFuncSetAttribute(k_proj_mma, cudaFuncAttributeMaxDynamicSharedMemorySize, SMEM_PROJ);
    cudaFuncSetAttribute(k_scores_mma, cudaFuncAttributeMaxDynamicSharedMemorySize, SMEM_SC);
    cudaFuncSetAttribute(k_out_h, cudaFuncAttributeMaxDynamicSharedMemorySize, SMEM_OUT);

    k_proj_mma  <<<dim3(NL / 64, NB), 256, SMEM_PROJ>>>(x, W1, W2);
    k_scores_mma<<<dim3(NIT, NJT, NB), 256, SMEM_SC>>>();
    k_out_h     <<<dim3(NL / 128, NC / 128, NB), 256, SMEM_OUT>>>(x, gam, out);
}